// round 5
// baseline (speedup 1.0000x reference)
#include <cuda_runtime.h>
#include <cstdint>

#define B_N   32
#define CIN   256
#define HW    3136
#define HW4   784
#define PX    100352          // B_N*HW
#define CO1   128
#define CO2   32
#define N_OUT (32*288*3136)

// ---------------- scratch (device globals; no allocations) ----------------
__device__ float    g_w1q[CIN], g_b1q[CIN];
__device__ float    g_bf[CO1], g_sw1[CO1];
__device__ int      g_wq1t[64*CO1];         // int8 packed, [k=ci/4][oc]
__device__ float    g_sw2[CO2];
__device__ int      g_wq2[CO2*288];         // [oc][tap*32 + ci/4]
__device__ unsigned g_max1, g_max2, g_maxb, g_maxy;
__device__ float    g_x2[PX*CO1];           // conv1 out fp32 NHWC (51.4MB)
__device__ int      g_x2q32[PX*32];         // x2 codes NHWC packed (12.8MB)

// ---------------- helpers ----------------
__device__ __forceinline__ float warpMax(float v) {
    #pragma unroll
    for (int o = 16; o; o >>= 1) v = fmaxf(v, __shfl_xor_sync(0xffffffffu, v, o));
    return v;
}
__device__ __forceinline__ float blockReduceMax(float v) {
    __shared__ float sm[8];
    float w = warpMax(v);
    if ((threadIdx.x & 31) == 0) sm[threadIdx.x >> 5] = w;
    __syncthreads();
    float r = (threadIdx.x < (blockDim.x >> 5)) ? sm[threadIdx.x] : 0.0f;
    r = warpMax(r);
    __syncthreads();
    return r;  // valid in warp 0
}
__device__ __forceinline__ float qclipf(float q, float lo, float hi) {
    return fminf(fmaxf(q, lo), hi);
}

// ---------------- K0: weight prep ----------------
__global__ void k_prep(const float* __restrict__ g1, const float* __restrict__ be1,
                       const float* __restrict__ m1, const float* __restrict__ v1,
                       const float* __restrict__ s_in_p, const float* __restrict__ w1c,
                       const float* __restrict__ g2, const float* __restrict__ be2,
                       const float* __restrict__ m2, const float* __restrict__ v2,
                       const float* __restrict__ w2c)
{
    int t = threadIdx.x;
    if (blockIdx.x == 0) {
        if (t == 0) { g_max1 = 0u; g_max2 = 0u; g_maxb = 0u; g_maxy = 0u; }
        float w1 = g1[t] / sqrtf(v1[t] + 1e-5f);
        float b1 = be1[t] - m1[t] * w1;
        float bm = blockReduceMax(fabsf(w1));
        __shared__ float s_sbn;
        if (t == 0) s_sbn = bm / 127.0f + 1e-8f;
        __syncthreads();
        float sbn = s_sbn;
        float c = qclipf(rintf(w1 / sbn), -128.0f, 127.0f);
        g_w1q[t] = c * sbn;
        float sc = s_in_p[0] * sbn;
        g_b1q[t] = rintf(b1 / sc) * sc;
    } else if (blockIdx.x == 1) {
        if (t < CO1) {
            float tt = g2[t] / sqrtf(v2[t] + 1e-5f);
            const float* wr = w1c + t * CIN;
            float mx = 0.0f;
            for (int c = 0; c < CIN; c++) mx = fmaxf(mx, fabsf(wr[c] * tt));
            float s = mx / 127.0f + 1e-8f;
            g_sw1[t] = s;
            g_bf[t]  = be2[t] - m2[t] * tt;
            for (int cw = 0; cw < 64; cw++) {
                unsigned word = 0;
                #pragma unroll
                for (int j = 0; j < 4; j++) {
                    float wf = wr[cw * 4 + j] * tt;
                    int qi = (int)qclipf(rintf(wf / s), -128.0f, 127.0f);
                    word |= ((unsigned)(qi & 0xff)) << (8 * j);
                }
                g_wq1t[cw * CO1 + t] = (int)word;      // transposed [k][oc]
            }
        }
    } else {
        if (t < CO2) {
            const float* wr = w2c + t * 1152;   // [128 ci][3][3]
            float mx = 0.0f;
            for (int k = 0; k < 1152; k++) mx = fmaxf(mx, fabsf(wr[k]));
            float s = mx / 127.0f + 1e-8f;
            g_sw2[t] = s;
            for (int tap = 0; tap < 9; tap++)
                for (int cw = 0; cw < 32; cw++) {
                    unsigned word = 0;
                    #pragma unroll
                    for (int j = 0; j < 4; j++) {
                        int qi = (int)qclipf(rintf(wr[(cw * 4 + j) * 9 + tap] / s),
                                             -128.0f, 127.0f);
                        word |= ((unsigned)(qi & 0xff)) << (8 * j);
                    }
                    g_wq2[t * 288 + tap * 32 + cw] = (int)word;
                }
        }
    }
}

// ------- K1: max relu(bn1(batch)) and max|batch|, plane-per-block --------
__global__ __launch_bounds__(256) void k_max1(const float4* __restrict__ batch4)
{
    int ci = blockIdx.x, b = blockIdx.y;
    const float4* p = batch4 + (b * CIN + ci) * HW4;
    float w = g_w1q[ci], bb = g_b1q[ci];
    float m1 = 0.0f, mb = 0.0f;
    for (int j = threadIdx.x; j < HW4; j += 256) {
        float4 v = p[j];
        m1 = fmaxf(m1, fmaxf(fmaf(v.x, w, bb), 0.0f));
        m1 = fmaxf(m1, fmaxf(fmaf(v.y, w, bb), 0.0f));
        m1 = fmaxf(m1, fmaxf(fmaf(v.z, w, bb), 0.0f));
        m1 = fmaxf(m1, fmaxf(fmaf(v.w, w, bb), 0.0f));
        mb = fmaxf(mb, fmaxf(fmaxf(fabsf(v.x), fabsf(v.y)),
                             fmaxf(fabsf(v.z), fabsf(v.w))));
    }
    float r1 = blockReduceMax(m1);
    if (threadIdx.x == 0) atomicMax(&g_max1, __float_as_uint(r1));
    float rb = blockReduceMax(mb);
    if (threadIdx.x == 0) atomicMax(&g_maxb, __float_as_uint(rb));
}

// ---- K2: fused bn1+quant+transpose + 1x1 int8 GEMM (128px x 128oc, K=256) ----
__global__ __launch_bounds__(256) void k_conv1(const float* __restrict__ batch)
{
    extern __shared__ int smem[];
    int* Ws = smem;                    // [64 k][132 oc-words]
    int* Bs = smem + 64 * 132;         // [64 k][132 px-words]
    float* sc1  = (float*)(Bs + 64 * 132);   // 128
    float* sb1  = sc1 + 128;                 // 128
    float* sw1s = sb1 + 128;                 // 256
    float* sb1s = sw1s + 256;                // 256
    int t = threadIdx.x;
    int p0 = blockIdx.x * 128;

    float sa1 = __uint_as_float(g_max1) / 127.0f + 1e-8f;
    float inv = 1.0f / sa1;
    if (t < 128) {
        float sc = sa1 * g_sw1[t];
        sc1[t] = sc;
        sb1[t] = rintf(g_bf[t] / sc) * sc;
    }
    sw1s[t] = g_w1q[t];
    sb1s[t] = g_b1q[t];
    __syncthreads();

    // weights: 8192 words, conflict-free (consecutive oc)
    #pragma unroll
    for (int i = 0; i < 32; i++) {
        int lin = t + 256 * i;
        int k = lin >> 7, oc = lin & 127;
        Ws[k * 132 + oc] = g_wq1t[lin];
    }
    // activations: thread-per-(k,px) word; 4 coalesced scalar loads,
    // pack codes in registers, single conflict-free STS.32
    #pragma unroll
    for (int i = 0; i < 32; i++) {
        int lin = t + 256 * i;                 // 8192 = 64k x 128px
        int k = lin >> 7, px = lin & 127;
        int pglob = p0 + px;
        int b = pglob / HW;
        int s = pglob - b * HW;
        const float* bp = batch + ((size_t)(b * CIN + 4 * k)) * HW + s;
        float f0 = bp[0], f1 = bp[HW], f2 = bp[2 * HW], f3 = bp[3 * HW];
        float4 wv = *(const float4*)&sw1s[4 * k];
        float4 bv = *(const float4*)&sb1s[4 * k];
        int q0 = (int)qclipf(rintf(fmaxf(fmaf(f0, wv.x, bv.x), 0.0f) * inv), 0.0f, 127.0f);
        int q1 = (int)qclipf(rintf(fmaxf(fmaf(f1, wv.y, bv.y), 0.0f) * inv), 0.0f, 127.0f);
        int q2 = (int)qclipf(rintf(fmaxf(fmaf(f2, wv.z, bv.z), 0.0f) * inv), 0.0f, 127.0f);
        int q3 = (int)qclipf(rintf(fmaxf(fmaf(f3, wv.w, bv.w), 0.0f) * inv), 0.0f, 127.0f);
        Bs[k * 132 + px] = q0 | (q1 << 8) | (q2 << 16) | (q3 << 24);
    }
    __syncthreads();

    int tx = t & 15, ty = t >> 4;              // tx: oc octet, ty: px octet
    int acc[64];
    #pragma unroll
    for (int i = 0; i < 64; i++) acc[i] = 0;
    const int* wp = Ws + 8 * tx;
    const int* bp = Bs + 8 * ty;
    #pragma unroll 2
    for (int k = 0; k < 64; k++) {
        int4 a0 = *(const int4*)(wp + k * 132);
        int4 a1 = *(const int4*)(wp + k * 132 + 4);
        int4 b0 = *(const int4*)(bp + k * 132);
        int4 b1 = *(const int4*)(bp + k * 132 + 4);
        int a[8] = {a0.x, a0.y, a0.z, a0.w, a1.x, a1.y, a1.z, a1.w};
        int bb[8] = {b0.x, b0.y, b0.z, b0.w, b1.x, b1.y, b1.z, b1.w};
        #pragma unroll
        for (int j = 0; j < 8; j++) {
            #pragma unroll
            for (int i2 = 0; i2 < 8; i2++)
                acc[j * 8 + i2] = __dp4a(bb[j], a[i2], acc[j * 8 + i2]);
        }
    }
    float m = 0.0f;
    #pragma unroll
    for (int j = 0; j < 8; j++) {
        int px = p0 + ty * 8 + j;
        float vals[8];
        #pragma unroll
        for (int i2 = 0; i2 < 8; i2++) {
            int oc = tx * 8 + i2;
            float v = fmaxf(fmaf((float)acc[j * 8 + i2], sc1[oc], sb1[oc]), 0.0f);
            vals[i2] = v; m = fmaxf(m, v);
        }
        float4* op = (float4*)&g_x2[px * 128 + tx * 8];
        op[0] = make_float4(vals[0], vals[1], vals[2], vals[3]);
        op[1] = make_float4(vals[4], vals[5], vals[6], vals[7]);
    }
    float bm = blockReduceMax(m);
    if (t == 0) atomicMax(&g_max2, __float_as_uint(bm));
}

// ---------------- K3: quantize x2 (fp32) -> int8 NHWC packed ----------------
__global__ void k_quant2()
{
    const int n = PX * 32;
    float inv = 1.0f / (__uint_as_float(g_max2) / 127.0f + 1e-8f);
    const float4* xp = (const float4*)g_x2;
    for (int i = blockIdx.x * blockDim.x + threadIdx.x; i < n;
         i += gridDim.x * blockDim.x) {
        float4 v = xp[i];
        int q0 = (int)qclipf(rintf(v.x * inv), 0.0f, 127.0f);
        int q1 = (int)qclipf(rintf(v.y * inv), 0.0f, 127.0f);
        int q2 = (int)qclipf(rintf(v.z * inv), 0.0f, 127.0f);
        int q3 = (int)qclipf(rintf(v.w * inv), 0.0f, 127.0f);
        g_x2q32[i] = q0 | (q1 << 8) | (q2 << 16) | (q3 << 24);
    }
}

// ---------------- K4: conv2 3x3 int8, 4 rows per block ----------------
__global__ __launch_bounds__(256) void k_conv2(float* __restrict__ out)
{
    extern __shared__ int smem[];
    int*   Xs   = smem;                    // [6 rows][58 cols] cells of 36 words
    int*   Wsm  = smem + 6 * 58 * 36;      // [32 oc][292]
    float* scmb = (float*)(Wsm + 32 * 292);
    int t = threadIdx.x;
    int h0 = blockIdx.x * 4, b = blockIdx.y;

    float sa2 = __uint_as_float(g_max2) / 127.0f + 1e-8f;
    if (t < 32) scmb[t] = sa2 * g_sw2[t];

    for (int lin = t; lin < 6 * 58 * 32; lin += 256) {
        int row = lin / (58 * 32);
        int rem = lin - row * (58 * 32);
        int col = rem >> 5, kw = rem & 31;
        int hh = h0 + row - 1;
        int val = 0;
        if (col >= 1 && col <= 56 && hh >= 0 && hh <= 55)
            val = g_x2q32[((b * HW) + hh * 56 + (col - 1)) * 32 + kw];
        Xs[(row * 58 + col) * 36 + kw] = val;
    }
    for (int lin = t; lin < 32 * 288; lin += 256) {
        int oc = lin / 288, j = lin - oc * 288;
        Wsm[oc * 292 + j] = g_wq2[lin];
    }
    __syncthreads();

    float m = 0.0f;
    if (t < 224) {
        int px = t % 56, ocg = t / 56;
        int acc[32];                       // [h][oc]
        #pragma unroll
        for (int i = 0; i < 32; i++) acc[i] = 0;
        const int4* X4 = (const int4*)Xs;
        const int4* W4 = (const int4*)Wsm + (ocg * 8) * 73;
        #pragma unroll 1
        for (int tap = 0; tap < 9; tap++) {
            int base = ((tap / 3) * 58 + px + tap % 3) * 9;
            const int4* w4 = W4 + tap * 8;
            #pragma unroll 2
            for (int kw4 = 0; kw4 < 8; kw4++) {
                int4 xv0 = X4[base + kw4];
                int4 xv1 = X4[base + 522 + kw4];
                int4 xv2 = X4[base + 1044 + kw4];
                int4 xv3 = X4[base + 1566 + kw4];
                #pragma unroll
                for (int o = 0; o < 8; o++) {
                    int4 wv = w4[o * 73 + kw4];
                    int a0 = acc[o], a1 = acc[8 + o], a2 = acc[16 + o], a3 = acc[24 + o];
                    a0 = __dp4a(xv0.x, wv.x, a0); a0 = __dp4a(xv0.y, wv.y, a0);
                    a0 = __dp4a(xv0.z, wv.z, a0); a0 = __dp4a(xv0.w, wv.w, a0);
                    a1 = __dp4a(xv1.x, wv.x, a1); a1 = __dp4a(xv1.y, wv.y, a1);
                    a1 = __dp4a(xv1.z, wv.z, a1); a1 = __dp4a(xv1.w, wv.w, a1);
                    a2 = __dp4a(xv2.x, wv.x, a2); a2 = __dp4a(xv2.y, wv.y, a2);
                    a2 = __dp4a(xv2.z, wv.z, a2); a2 = __dp4a(xv2.w, wv.w, a2);
                    a3 = __dp4a(xv3.x, wv.x, a3); a3 = __dp4a(xv3.y, wv.y, a3);
                    a3 = __dp4a(xv3.z, wv.z, a3); a3 = __dp4a(xv3.w, wv.w, a3);
                    acc[o] = a0; acc[8 + o] = a1; acc[16 + o] = a2; acc[24 + o] = a3;
                }
            }
        }
        #pragma unroll
        for (int hh = 0; hh < 4; hh++) {
            #pragma unroll
            for (int o = 0; o < 8; o++) {
                int oc = ocg * 8 + o;
                float v = (float)acc[hh * 8 + o] * scmb[oc];
                out[((b * 288) + 256 + oc) * HW + (h0 + hh) * 56 + px] = v;
                m = fmaxf(m, fabsf(v));
            }
        }
    }
    float bm = blockReduceMax(m);
    if (t == 0) atomicMax(&g_maxy, __float_as_uint(bm));
}

// ------ K5: output requant, plane-per-block (batch, y regions, tail) --------
__global__ __launch_bounds__(256) void k_out(const float4* __restrict__ batch4,
                                             float4* __restrict__ out4,
                                             float* __restrict__ out, int out_size)
{
    int c = blockIdx.x, b = blockIdx.y;
    float s = fmaxf(__uint_as_float(g_maxb), __uint_as_float(g_maxy)) / 127.0f + 1e-8f;
    float inv = 1.0f / s;
    float4* dst = out4 + (b * 288 + c) * HW4;
    if (c < CIN) {
        const float4* src = batch4 + (b * CIN + c) * HW4;
        for (int j = threadIdx.x; j < HW4; j += 256) {
            float4 v = src[j];
            v.x = qclipf(rintf(v.x * inv), -128.0f, 127.0f) * s;
            v.y = qclipf(rintf(v.y * inv), -128.0f, 127.0f) * s;
            v.z = qclipf(rintf(v.z * inv), -128.0f, 127.0f) * s;
            v.w = qclipf(rintf(v.w * inv), -128.0f, 127.0f) * s;
            dst[j] = v;
        }
    } else {
        for (int j = threadIdx.x; j < HW4; j += 256) {
            float4 v = dst[j];
            v.x = qclipf(rintf(v.x * inv), -128.0f, 127.0f) * s;
            v.y = qclipf(rintf(v.y * inv), -128.0f, 127.0f) * s;
            v.z = qclipf(rintf(v.z * inv), -128.0f, 127.0f) * s;
            v.w = qclipf(rintf(v.w * inv), -128.0f, 127.0f) * s;
            dst[j] = v;
        }
    }
    if (c == 0 && b == 0 && threadIdx.x == 0)
        for (int k = N_OUT; k < out_size; k++) out[k] = s;
}

extern "C" void kernel_launch(void* const* d_in, const int* in_sizes, int n_in,
                              void* d_out, int out_size)
{
    const float* batch = (const float*)d_in[0];
    const float* s_in  = (const float*)d_in[1];
    const float* g1    = (const float*)d_in[2];
    const float* be1   = (const float*)d_in[3];
    const float* m1    = (const float*)d_in[4];
    const float* v1    = (const float*)d_in[5];
    const float* w1c   = (const float*)d_in[6];
    const float* g2    = (const float*)d_in[7];
    const float* be2   = (const float*)d_in[8];
    const float* m2    = (const float*)d_in[9];
    const float* v2    = (const float*)d_in[10];
    const float* w2c   = (const float*)d_in[11];
    float* out = (float*)d_out;

    static bool attr_done = false;
    if (!attr_done) {
        cudaFuncSetAttribute(k_conv1, cudaFuncAttributeMaxDynamicSharedMemorySize, 70656);
        cudaFuncSetAttribute(k_conv2, cudaFuncAttributeMaxDynamicSharedMemorySize, 87616);
        attr_done = true;
    }

    k_prep<<<3, 256>>>(g1, be1, m1, v1, s_in, w1c, g2, be2, m2, v2, w2c);
    k_max1<<<dim3(CIN, B_N), 256>>>((const float4*)batch);
    k_conv1<<<PX / 128, 256, 70656>>>(batch);
    k_quant2<<<2048, 256>>>();
    k_conv2<<<dim3(14, 32), 256, 87616>>>(out);
    k_out<<<dim3(288, B_N), 256>>>((const float4*)batch, (float4*)out, out, out_size);
}

// round 6
// speedup vs baseline: 1.0220x; 1.0220x over previous
#include <cuda_runtime.h>
#include <cuda_bf16.h>
#include <cstdint>

#define B_N   32
#define CIN   256
#define HW    3136
#define HW4   784
#define PX    100352          // B_N*HW
#define CO1   128
#define CO2   32
#define N_OUT (32*288*3136)

// ---------------- scratch (device globals; no allocations) ----------------
__device__ float    g_w1q[CIN], g_b1q[CIN];
__device__ float    g_bf[CO1], g_sw1[CO1];
__device__ __nv_bfloat16 g_w1cb[CO1*256];   // conv1 weight codes as bf16 [oc][k]
__device__ float    g_sw2[CO2];
__device__ int      g_wq2[CO2*288];         // [oc][tap*32 + ci/4]
__device__ unsigned g_max1, g_max2, g_maxb, g_maxy;
__device__ float    g_x2[PX*CO1];           // conv1 out fp32 NHWC (51.4MB)
__device__ int      g_x2q32[PX*32];         // x2 codes NHWC packed (12.8MB)

// ---------------- helpers ----------------
__device__ __forceinline__ float warpMax(float v) {
    #pragma unroll
    for (int o = 16; o; o >>= 1) v = fmaxf(v, __shfl_xor_sync(0xffffffffu, v, o));
    return v;
}
__device__ __forceinline__ float blockReduceMax(float v) {
    __shared__ float sm[8];
    float w = warpMax(v);
    if ((threadIdx.x & 31) == 0) sm[threadIdx.x >> 5] = w;
    __syncthreads();
    float r = (threadIdx.x < (blockDim.x >> 5)) ? sm[threadIdx.x] : 0.0f;
    r = warpMax(r);
    __syncthreads();
    return r;  // valid in warp 0
}
__device__ __forceinline__ float qclipf(float q, float lo, float hi) {
    return fminf(fmaxf(q, lo), hi);
}
__device__ __forceinline__ uint32_t smem_u32(const void* p) {
    return (uint32_t)__cvta_generic_to_shared(p);
}
__device__ __forceinline__ void ldsm_x4(uint32_t& r0, uint32_t& r1,
                                        uint32_t& r2, uint32_t& r3, uint32_t a) {
    asm volatile("ldmatrix.sync.aligned.m8n8.x4.shared.b16 {%0,%1,%2,%3}, [%4];"
                 : "=r"(r0), "=r"(r1), "=r"(r2), "=r"(r3) : "r"(a));
}
__device__ __forceinline__ void ldsm_x2(uint32_t& r0, uint32_t& r1, uint32_t a) {
    asm volatile("ldmatrix.sync.aligned.m8n8.x2.shared.b16 {%0,%1}, [%2];"
                 : "=r"(r0), "=r"(r1) : "r"(a));
}
__device__ __forceinline__ void mma_bf16(float* d, const uint32_t* a, const uint32_t* b) {
    asm volatile(
        "mma.sync.aligned.m16n8k16.row.col.f32.bf16.bf16.f32 "
        "{%0,%1,%2,%3},{%4,%5,%6,%7},{%8,%9},{%0,%1,%2,%3};"
        : "+f"(d[0]), "+f"(d[1]), "+f"(d[2]), "+f"(d[3])
        : "r"(a[0]), "r"(a[1]), "r"(a[2]), "r"(a[3]), "r"(b[0]), "r"(b[1]));
}

// ---------------- K0a: bn1 fold + max init ----------------
__global__ void k_prep1(const float* __restrict__ g1, const float* __restrict__ be1,
                        const float* __restrict__ m1, const float* __restrict__ v1,
                        const float* __restrict__ s_in_p)
{
    int t = threadIdx.x;
    if (t == 0) { g_max1 = 0u; g_max2 = 0u; g_maxb = 0u; g_maxy = 0u; }
    float w1 = g1[t] / sqrtf(v1[t] + 1e-5f);
    float b1 = be1[t] - m1[t] * w1;
    float bm = blockReduceMax(fabsf(w1));
    __shared__ float s_sbn;
    if (t == 0) s_sbn = bm / 127.0f + 1e-8f;
    __syncthreads();
    float sbn = s_sbn;
    float c = qclipf(rintf(w1 / sbn), -128.0f, 127.0f);
    g_w1q[t] = c * sbn;
    float sc = s_in_p[0] * sbn;
    g_b1q[t] = rintf(b1 / sc) * sc;
}

// ---------------- K0b: conv weight quantization ----------------
__global__ void k_prep2(const float* __restrict__ w1c,
                        const float* __restrict__ g2, const float* __restrict__ be2,
                        const float* __restrict__ m2, const float* __restrict__ v2,
                        const float* __restrict__ w2c)
{
    int t = threadIdx.x;
    if (blockIdx.x == 0) {
        if (t < CO1) {
            float tt = g2[t] / sqrtf(v2[t] + 1e-5f);
            const float* wr = w1c + t * CIN;
            float mx = 0.0f;
            for (int c = 0; c < CIN; c++) mx = fmaxf(mx, fabsf(wr[c] * tt));
            float s = mx / 127.0f + 1e-8f;
            g_sw1[t] = s;
            g_bf[t]  = be2[t] - m2[t] * tt;
            for (int c = 0; c < CIN; c++) {
                float code = qclipf(rintf(wr[c] * tt / s), -128.0f, 127.0f);
                g_w1cb[t * 256 + c] = __float2bfloat16(code);   // exact
            }
        }
    } else {
        if (t < CO2) {
            const float* wr = w2c + t * 1152;   // [128 ci][3][3]
            float mx = 0.0f;
            for (int k = 0; k < 1152; k++) mx = fmaxf(mx, fabsf(wr[k]));
            float s = mx / 127.0f + 1e-8f;
            g_sw2[t] = s;
            for (int tap = 0; tap < 9; tap++)
                for (int cw = 0; cw < 32; cw++) {
                    unsigned word = 0;
                    #pragma unroll
                    for (int j = 0; j < 4; j++) {
                        int qi = (int)qclipf(rintf(wr[(cw * 4 + j) * 9 + tap] / s),
                                             -128.0f, 127.0f);
                        word |= ((unsigned)(qi & 0xff)) << (8 * j);
                    }
                    g_wq2[t * 288 + tap * 32 + cw] = (int)word;
                }
        }
    }
}

// ------- K1: max relu(bn1(batch)) and max|batch|, plane-per-block --------
__global__ __launch_bounds__(256) void k_max1(const float4* __restrict__ batch4)
{
    int ci = blockIdx.x, b = blockIdx.y;
    const float4* p = batch4 + (b * CIN + ci) * HW4;
    float w = g_w1q[ci], bb = g_b1q[ci];
    float m1 = 0.0f, mb = 0.0f;
    for (int j = threadIdx.x; j < HW4; j += 256) {
        float4 v = p[j];
        m1 = fmaxf(m1, fmaxf(fmaf(v.x, w, bb), 0.0f));
        m1 = fmaxf(m1, fmaxf(fmaf(v.y, w, bb), 0.0f));
        m1 = fmaxf(m1, fmaxf(fmaf(v.z, w, bb), 0.0f));
        m1 = fmaxf(m1, fmaxf(fmaf(v.w, w, bb), 0.0f));
        mb = fmaxf(mb, fmaxf(fmaxf(fabsf(v.x), fabsf(v.y)),
                             fmaxf(fabsf(v.z), fabsf(v.w))));
    }
    float r1 = blockReduceMax(m1);
    if (threadIdx.x == 0) atomicMax(&g_max1, __float_as_uint(r1));
    float rb = blockReduceMax(mb);
    if (threadIdx.x == 0) atomicMax(&g_maxb, __float_as_uint(rb));
}

// ---- K2: fused bn1+quant + 1x1 conv via bf16 mma.sync (128px x 128oc, K=256) ----
// smem rows padded to 264 bf16 (528B): ldmatrix 8-row accesses hit distinct banks.
__global__ __launch_bounds__(256) void k_conv1(const float* __restrict__ batch)
{
    extern __shared__ __nv_bfloat16 smemb[];
    __nv_bfloat16* Xs = smemb;                 // [128 px][264]
    __nv_bfloat16* Ws = smemb + 128 * 264;     // [128 oc][264]
    float* sc1  = (float*)(smemb + 2 * 128 * 264);  // 128
    float* sb1  = sc1 + 128;                        // 128
    float* sw1s = sb1 + 128;                        // 256
    float* sb1s = sw1s + 256;                       // 256
    int t = threadIdx.x;
    int p0 = blockIdx.x * 128;

    float sa1 = __uint_as_float(g_max1) / 127.0f + 1e-8f;
    float inv = 1.0f / sa1;
    if (t < 128) {
        float sc = sa1 * g_sw1[t];
        sc1[t] = sc;
        sb1[t] = rintf(g_bf[t] / sc) * sc;
    }
    sw1s[t] = g_w1q[t];
    sb1s[t] = g_b1q[t];
    __syncthreads();

    // weights: 128oc x 256k bf16, uint4 (8 bf16) chunks, coalesced + conflict-free
    #pragma unroll
    for (int i = 0; i < 16; i++) {
        int lin = t + 256 * i;                  // 4096 uint4
        int oc = lin >> 5, j = lin & 31;
        uint4 v = ((const uint4*)g_w1cb)[oc * 32 + j];
        *(uint4*)(Ws + oc * 264 + 8 * j) = v;
    }
    // activations: thread-per-(k,px); 4 coalesced scalar loads, bn+relu+quant,
    // pack 4 bf16 codes, one STS.64
    #pragma unroll
    for (int i = 0; i < 32; i++) {
        int lin = t + 256 * i;                  // 8192 = 64k x 128px
        int k = lin >> 7, px = lin & 127;
        int pglob = p0 + px;
        int b = pglob / HW;
        int s = pglob - b * HW;
        const float* bp = batch + ((size_t)(b * CIN + 4 * k)) * HW + s;
        float f0 = bp[0], f1 = bp[HW], f2 = bp[2 * HW], f3 = bp[3 * HW];
        float4 wv = *(const float4*)&sw1s[4 * k];
        float4 bv = *(const float4*)&sb1s[4 * k];
        float q0 = qclipf(rintf(fmaxf(fmaf(f0, wv.x, bv.x), 0.0f) * inv), 0.0f, 127.0f);
        float q1 = qclipf(rintf(fmaxf(fmaf(f1, wv.y, bv.y), 0.0f) * inv), 0.0f, 127.0f);
        float q2 = qclipf(rintf(fmaxf(fmaf(f2, wv.z, bv.z), 0.0f) * inv), 0.0f, 127.0f);
        float q3 = qclipf(rintf(fmaxf(fmaf(f3, wv.w, bv.w), 0.0f) * inv), 0.0f, 127.0f);
        __nv_bfloat162 h01 = __floats2bfloat162_rn(q0, q1);  // exact (int codes)
        __nv_bfloat162 h23 = __floats2bfloat162_rn(q2, q3);
        uint2 pk;
        pk.x = *(uint32_t*)&h01;
        pk.y = *(uint32_t*)&h23;
        *(uint2*)(Xs + px * 264 + 4 * k) = pk;
    }
    __syncthreads();

    // warp tiling: 8 warps = 2 px-groups(64) x 4 oc-groups(32)
    int wid = t >> 5, l = t & 31;
    int pxg = wid & 1, ocg = wid >> 1;
    uint32_t xs0 = smem_u32(Xs), ws0 = smem_u32(Ws);

    uint32_t aaddr[4], baddr[4];
    #pragma unroll
    for (int mf = 0; mf < 4; mf++)
        aaddr[mf] = xs0 + ((pxg * 64 + mf * 16 + (l & 15)) * 264 + (l >> 4) * 8) * 2;
    #pragma unroll
    for (int nf = 0; nf < 4; nf++)
        baddr[nf] = ws0 + ((ocg * 32 + nf * 8 + (l & 7)) * 264 + ((l >> 3) & 1) * 8) * 2;

    float acc[4][4][4];
    #pragma unroll
    for (int mf = 0; mf < 4; mf++)
        #pragma unroll
        for (int nf = 0; nf < 4; nf++)
            #pragma unroll
            for (int r = 0; r < 4; r++) acc[mf][nf][r] = 0.0f;

    #pragma unroll 2
    for (int ks = 0; ks < 16; ks++) {
        uint32_t a[4][4], bfr[4][2];
        #pragma unroll
        for (int mf = 0; mf < 4; mf++)
            ldsm_x4(a[mf][0], a[mf][1], a[mf][2], a[mf][3], aaddr[mf] + ks * 32);
        #pragma unroll
        for (int nf = 0; nf < 4; nf++)
            ldsm_x2(bfr[nf][0], bfr[nf][1], baddr[nf] + ks * 32);
        #pragma unroll
        for (int mf = 0; mf < 4; mf++)
            #pragma unroll
            for (int nf = 0; nf < 4; nf++)
                mma_bf16(acc[mf][nf], a[mf], bfr[nf]);
    }

    // epilogue: scale+bias+relu, write fp32 NHWC, track max
    float m = 0.0f;
    #pragma unroll
    for (int mf = 0; mf < 4; mf++) {
        int pxa = p0 + pxg * 64 + mf * 16 + (l >> 2);
        #pragma unroll
        for (int nf = 0; nf < 4; nf++) {
            int oc = ocg * 32 + nf * 8 + (l & 3) * 2;
            float s0 = sc1[oc], s1 = sc1[oc + 1];
            float bb0 = sb1[oc], bb1 = sb1[oc + 1];
            float v0 = fmaxf(fmaf(acc[mf][nf][0], s0, bb0), 0.0f);
            float v1 = fmaxf(fmaf(acc[mf][nf][1], s1, bb1), 0.0f);
            float v2 = fmaxf(fmaf(acc[mf][nf][2], s0, bb0), 0.0f);
            float v3 = fmaxf(fmaf(acc[mf][nf][3], s1, bb1), 0.0f);
            m = fmaxf(m, fmaxf(fmaxf(v0, v1), fmaxf(v2, v3)));
            *(float2*)&g_x2[(size_t)pxa * 128 + oc]       = make_float2(v0, v1);
            *(float2*)&g_x2[(size_t)(pxa + 8) * 128 + oc] = make_float2(v2, v3);
        }
    }
    float bm = blockReduceMax(m);
    if (t == 0) atomicMax(&g_max2, __float_as_uint(bm));
}

// ---------------- K3: quantize x2 (fp32) -> int8 NHWC packed ----------------
__global__ void k_quant2()
{
    const int n = PX * 32;
    float inv = 1.0f / (__uint_as_float(g_max2) / 127.0f + 1e-8f);
    const float4* xp = (const float4*)g_x2;
    for (int i = blockIdx.x * blockDim.x + threadIdx.x; i < n;
         i += gridDim.x * blockDim.x) {
        float4 v = xp[i];
        int q0 = (int)qclipf(rintf(v.x * inv), 0.0f, 127.0f);
        int q1 = (int)qclipf(rintf(v.y * inv), 0.0f, 127.0f);
        int q2 = (int)qclipf(rintf(v.z * inv), 0.0f, 127.0f);
        int q3 = (int)qclipf(rintf(v.w * inv), 0.0f, 127.0f);
        g_x2q32[i] = q0 | (q1 << 8) | (q2 << 16) | (q3 << 24);
    }
}

// ---------------- K4: conv2 3x3 int8, 4 rows per block ----------------
__global__ __launch_bounds__(256) void k_conv2(float* __restrict__ out)
{
    extern __shared__ int smem[];
    int*   Xs   = smem;                    // [6 rows][58 cols] cells of 36 words
    int*   Wsm  = smem + 6 * 58 * 36;      // [32 oc][292]
    float* scmb = (float*)(Wsm + 32 * 292);
    int t = threadIdx.x;
    int h0 = blockIdx.x * 4, b = blockIdx.y;

    float sa2 = __uint_as_float(g_max2) / 127.0f + 1e-8f;
    if (t < 32) scmb[t] = sa2 * g_sw2[t];

    for (int lin = t; lin < 6 * 58 * 32; lin += 256) {
        int row = lin / (58 * 32);
        int rem = lin - row * (58 * 32);
        int col = rem >> 5, kw = rem & 31;
        int hh = h0 + row - 1;
        int val = 0;
        if (col >= 1 && col <= 56 && hh >= 0 && hh <= 55)
            val = g_x2q32[((b * HW) + hh * 56 + (col - 1)) * 32 + kw];
        Xs[(row * 58 + col) * 36 + kw] = val;
    }
    for (int lin = t; lin < 32 * 288; lin += 256) {
        int oc = lin / 288, j = lin - oc * 288;
        Wsm[oc * 292 + j] = g_wq2[lin];
    }
    __syncthreads();

    float m = 0.0f;
    if (t < 224) {
        int px = t % 56, ocg = t / 56;
        int acc[32];                       // [h][oc]
        #pragma unroll
        for (int i = 0; i < 32; i++) acc[i] = 0;
        const int4* X4 = (const int4*)Xs;
        const int4* W4 = (const int4*)Wsm + (ocg * 8) * 73;
        #pragma unroll 1
        for (int tap = 0; tap < 9; tap++) {
            int base = ((tap / 3) * 58 + px + tap % 3) * 9;
            const int4* w4 = W4 + tap * 8;
            #pragma unroll 2
            for (int kw4 = 0; kw4 < 8; kw4++) {
                int4 xv0 = X4[base + kw4];
                int4 xv1 = X4[base + 522 + kw4];
                int4 xv2 = X4[base + 1044 + kw4];
                int4 xv3 = X4[base + 1566 + kw4];
                #pragma unroll
                for (int o = 0; o < 8; o++) {
                    int4 wv = w4[o * 73 + kw4];
                    int a0 = acc[o], a1 = acc[8 + o], a2 = acc[16 + o], a3 = acc[24 + o];
                    a0 = __dp4a(xv0.x, wv.x, a0); a0 = __dp4a(xv0.y, wv.y, a0);
                    a0 = __dp4a(xv0.z, wv.z, a0); a0 = __dp4a(xv0.w, wv.w, a0);
                    a1 = __dp4a(xv1.x, wv.x, a1); a1 = __dp4a(xv1.y, wv.y, a1);
                    a1 = __dp4a(xv1.z, wv.z, a1); a1 = __dp4a(xv1.w, wv.w, a1);
                    a2 = __dp4a(xv2.x, wv.x, a2); a2 = __dp4a(xv2.y, wv.y, a2);
                    a2 = __dp4a(xv2.z, wv.z, a2); a2 = __dp4a(xv2.w, wv.w, a2);
                    a3 = __dp4a(xv3.x, wv.x, a3); a3 = __dp4a(xv3.y, wv.y, a3);
                    a3 = __dp4a(xv3.z, wv.z, a3); a3 = __dp4a(xv3.w, wv.w, a3);
                    acc[o] = a0; acc[8 + o] = a1; acc[16 + o] = a2; acc[24 + o] = a3;
                }
            }
        }
        #pragma unroll
        for (int hh = 0; hh < 4; hh++) {
            #pragma unroll
            for (int o = 0; o < 8; o++) {
                int oc = ocg * 8 + o;
                float v = (float)acc[hh * 8 + o] * scmb[oc];
                out[((b * 288) + 256 + oc) * HW + (h0 + hh) * 56 + px] = v;
                m = fmaxf(m, fabsf(v));
            }
        }
    }
    float bm = blockReduceMax(m);
    if (t == 0) atomicMax(&g_maxy, __float_as_uint(bm));
}

// ------ K5: output requant, plane-per-block (batch, y regions, tail) --------
__global__ __launch_bounds__(256) void k_out(const float4* __restrict__ batch4,
                                             float4* __restrict__ out4,
                                             float* __restrict__ out, int out_size)
{
    int c = blockIdx.x, b = blockIdx.y;
    float s = fmaxf(__uint_as_float(g_maxb), __uint_as_float(g_maxy)) / 127.0f + 1e-8f;
    float inv = 1.0f / s;
    float4* dst = out4 + (b * 288 + c) * HW4;
    if (c < CIN) {
        const float4* src = batch4 + (b * CIN + c) * HW4;
        for (int j = threadIdx.x; j < HW4; j += 256) {
            float4 v = src[j];
            v.x = qclipf(rintf(v.x * inv), -128.0f, 127.0f) * s;
            v.y = qclipf(rintf(v.y * inv), -128.0f, 127.0f) * s;
            v.z = qclipf(rintf(v.z * inv), -128.0f, 127.0f) * s;
            v.w = qclipf(rintf(v.w * inv), -128.0f, 127.0f) * s;
            dst[j] = v;
        }
    } else {
        for (int j = threadIdx.x; j < HW4; j += 256) {
            float4 v = dst[j];
            v.x = qclipf(rintf(v.x * inv), -128.0f, 127.0f) * s;
            v.y = qclipf(rintf(v.y * inv), -128.0f, 127.0f) * s;
            v.z = qclipf(rintf(v.z * inv), -128.0f, 127.0f) * s;
            v.w = qclipf(rintf(v.w * inv), -128.0f, 127.0f) * s;
            dst[j] = v;
        }
    }
    if (c == 0 && b == 0 && threadIdx.x == 0)
        for (int k = N_OUT; k < out_size; k++) out[k] = s;
}

extern "C" void kernel_launch(void* const* d_in, const int* in_sizes, int n_in,
                              void* d_out, int out_size)
{
    const float* batch = (const float*)d_in[0];
    const float* s_in  = (const float*)d_in[1];
    const float* g1    = (const float*)d_in[2];
    const float* be1   = (const float*)d_in[3];
    const float* m1    = (const float*)d_in[4];
    const float* v1    = (const float*)d_in[5];
    const float* w1c   = (const float*)d_in[6];
    const float* g2    = (const float*)d_in[7];
    const float* be2   = (const float*)d_in[8];
    const float* m2    = (const float*)d_in[9];
    const float* v2    = (const float*)d_in[10];
    const float* w2c   = (const float*)d_in[11];
    float* out = (float*)d_out;

    const int CONV1_SMEM = 2 * 128 * 264 * 2 + (128 + 128 + 256 + 256) * 4; // 138240
    static bool attr_done = false;
    if (!attr_done) {
        cudaFuncSetAttribute(k_conv1, cudaFuncAttributeMaxDynamicSharedMemorySize, CONV1_SMEM);
        cudaFuncSetAttribute(k_conv2, cudaFuncAttributeMaxDynamicSharedMemorySize, 87616);
        attr_done = true;
    }

    k_prep1<<<1, 256>>>(g1, be1, m1, v1, s_in);                 // launch 0
    k_prep2<<<2, 256>>>(w1c, g2, be2, m2, v2, w2c);             // launch 1
    k_max1<<<dim3(CIN, B_N), 256>>>((const float4*)batch);      // launch 2
    k_conv1<<<PX / 128, 256, CONV1_SMEM>>>(batch);              // launch 3 (profiled)
    k_quant2<<<2048, 256>>>();                                  // launch 4
    k_conv2<<<dim3(14, 32), 256, 87616>>>(out);                 // launch 5
    k_out<<<dim3(288, B_N), 256>>>((const float4*)batch, (float4*)out, out, out_size);
}

// round 7
// speedup vs baseline: 1.1278x; 1.1035x over previous
#include <cuda_runtime.h>
#include <cuda_bf16.h>
#include <cstdint>

#define B_N   32
#define CIN   256
#define HW    3136
#define HW4   784
#define PX    100352          // B_N*HW
#define CO1   128
#define CO2   32
#define N_OUT (32*288*3136)

// ---------------- scratch (device globals; no allocations) ----------------
__device__ float    g_w1q[CIN], g_b1q[CIN];
__device__ float    g_bf[CO1], g_sw1[CO1];
__device__ __nv_bfloat16 g_w1cb[CO1*256];   // conv1 weight codes bf16 [oc][k]
__device__ float    g_sw2[CO2];
__device__ __nv_bfloat16 g_w2cb[CO2*1160];  // conv2 weight codes bf16 [oc][tap*128+ci], stride 1160
__device__ unsigned g_max1, g_max2, g_maxb, g_maxy;
__device__ float    g_x2[PX*CO1];           // conv1 out fp32 NHWC (51.4MB)
__device__ __nv_bfloat16 g_x2cb[PX*CO1];    // x2 codes bf16 NHWC (25.7MB)

// ---------------- helpers ----------------
__device__ __forceinline__ float warpMax(float v) {
    #pragma unroll
    for (int o = 16; o; o >>= 1) v = fmaxf(v, __shfl_xor_sync(0xffffffffu, v, o));
    return v;
}
__device__ __forceinline__ float blockReduceMax(float v) {
    __shared__ float sm[16];
    float w = warpMax(v);
    if ((threadIdx.x & 31) == 0) sm[threadIdx.x >> 5] = w;
    __syncthreads();
    float r = (threadIdx.x < (blockDim.x >> 5)) ? sm[threadIdx.x] : 0.0f;
    r = warpMax(r);
    __syncthreads();
    return r;  // valid in warp 0
}
__device__ __forceinline__ float qclipf(float q, float lo, float hi) {
    return fminf(fmaxf(q, lo), hi);
}
__device__ __forceinline__ uint32_t smem_u32(const void* p) {
    return (uint32_t)__cvta_generic_to_shared(p);
}
__device__ __forceinline__ void ldsm_x4(uint32_t& r0, uint32_t& r1,
                                        uint32_t& r2, uint32_t& r3, uint32_t a) {
    asm volatile("ldmatrix.sync.aligned.m8n8.x4.shared.b16 {%0,%1,%2,%3}, [%4];"
                 : "=r"(r0), "=r"(r1), "=r"(r2), "=r"(r3) : "r"(a));
}
__device__ __forceinline__ void ldsm_x2(uint32_t& r0, uint32_t& r1, uint32_t a) {
    asm volatile("ldmatrix.sync.aligned.m8n8.x2.shared.b16 {%0,%1}, [%2];"
                 : "=r"(r0), "=r"(r1) : "r"(a));
}
__device__ __forceinline__ void mma_bf16(float* d, const uint32_t* a, const uint32_t* b) {
    asm volatile(
        "mma.sync.aligned.m16n8k16.row.col.f32.bf16.bf16.f32 "
        "{%0,%1,%2,%3},{%4,%5,%6,%7},{%8,%9},{%0,%1,%2,%3};"
        : "+f"(d[0]), "+f"(d[1]), "+f"(d[2]), "+f"(d[3])
        : "r"(a[0]), "r"(a[1]), "r"(a[2]), "r"(a[3]), "r"(b[0]), "r"(b[1]));
}

// ---------------- K0a: bn1 fold + max init ----------------
__global__ void k_prep1(const float* __restrict__ g1, const float* __restrict__ be1,
                        const float* __restrict__ m1, const float* __restrict__ v1,
                        const float* __restrict__ s_in_p)
{
    int t = threadIdx.x;
    if (t == 0) { g_max1 = 0u; g_max2 = 0u; g_maxb = 0u; g_maxy = 0u; }
    float w1 = g1[t] / sqrtf(v1[t] + 1e-5f);
    float b1 = be1[t] - m1[t] * w1;
    float bm = blockReduceMax(fabsf(w1));
    __shared__ float s_sbn;
    if (t == 0) s_sbn = bm / 127.0f + 1e-8f;
    __syncthreads();
    float sbn = s_sbn;
    float c = qclipf(rintf(w1 / sbn), -128.0f, 127.0f);
    g_w1q[t] = c * sbn;
    float sc = s_in_p[0] * sbn;
    g_b1q[t] = rintf(b1 / sc) * sc;
}

// ---------------- K0b: conv weight quantization ----------------
__global__ void k_prep2(const float* __restrict__ w1c,
                        const float* __restrict__ g2, const float* __restrict__ be2,
                        const float* __restrict__ m2, const float* __restrict__ v2,
                        const float* __restrict__ w2c)
{
    int t = threadIdx.x;
    if (blockIdx.x == 0) {
        if (t < CO1) {
            float tt = g2[t] / sqrtf(v2[t] + 1e-5f);
            const float* wr = w1c + t * CIN;
            float mx = 0.0f;
            for (int c = 0; c < CIN; c++) mx = fmaxf(mx, fabsf(wr[c] * tt));
            float s = mx / 127.0f + 1e-8f;
            g_sw1[t] = s;
            g_bf[t]  = be2[t] - m2[t] * tt;
            for (int c = 0; c < CIN; c++) {
                float code = qclipf(rintf(wr[c] * tt / s), -128.0f, 127.0f);
                g_w1cb[t * 256 + c] = __float2bfloat16(code);   // exact
            }
        }
    } else {
        if (t < CO2) {
            const float* wr = w2c + t * 1152;   // [128 ci][3][3]
            float mx = 0.0f;
            for (int k = 0; k < 1152; k++) mx = fmaxf(mx, fabsf(wr[k]));
            float s = mx / 127.0f + 1e-8f;
            g_sw2[t] = s;
            for (int tap = 0; tap < 9; tap++)
                for (int ci = 0; ci < 128; ci++) {
                    float code = qclipf(rintf(wr[ci * 9 + tap] / s), -128.0f, 127.0f);
                    g_w2cb[t * 1160 + tap * 128 + ci] = __float2bfloat16(code);
                }
        }
    }
}

// ------- K1: max relu(bn1(batch)) and max|batch|, plane-per-block --------
__global__ __launch_bounds__(256) void k_max1(const float4* __restrict__ batch4)
{
    int ci = blockIdx.x, b = blockIdx.y;
    const float4* p = batch4 + (b * CIN + ci) * HW4;
    float w = g_w1q[ci], bb = g_b1q[ci];
    float m1 = 0.0f, mb = 0.0f;
    for (int j = threadIdx.x; j < HW4; j += 256) {
        float4 v = p[j];
        m1 = fmaxf(m1, fmaxf(fmaf(v.x, w, bb), 0.0f));
        m1 = fmaxf(m1, fmaxf(fmaf(v.y, w, bb), 0.0f));
        m1 = fmaxf(m1, fmaxf(fmaf(v.z, w, bb), 0.0f));
        m1 = fmaxf(m1, fmaxf(fmaf(v.w, w, bb), 0.0f));
        mb = fmaxf(mb, fmaxf(fmaxf(fabsf(v.x), fabsf(v.y)),
                             fmaxf(fabsf(v.z), fabsf(v.w))));
    }
    float r1 = blockReduceMax(m1);
    if (threadIdx.x == 0) atomicMax(&g_max1, __float_as_uint(r1));
    float rb = blockReduceMax(mb);
    if (threadIdx.x == 0) atomicMax(&g_maxb, __float_as_uint(rb));
}

// ---- K2: fused bn1+quant + 1x1 conv via bf16 mma (256px x 128oc, K=256) ----
__global__ __launch_bounds__(512) void k_conv1(const float* __restrict__ batch)
{
    extern __shared__ __nv_bfloat16 smemb[];
    __nv_bfloat16* Xs = smemb;                 // [256 px][264]
    __nv_bfloat16* Ws = smemb + 256 * 264;     // [128 oc][264]
    float* sc1  = (float*)(smemb + 384 * 264);
    float* sb1  = sc1 + 128;
    float* sw1s = sb1 + 128;                   // 256
    float* sb1s = sw1s + 256;                  // 256
    int t = threadIdx.x;
    int p0 = blockIdx.x * 256;

    float sa1 = __uint_as_float(g_max1) / 127.0f + 1e-8f;
    float inv = 1.0f / sa1;
    if (t < 128) {
        float sc = sa1 * g_sw1[t];
        sc1[t] = sc;
        sb1[t] = rintf(g_bf[t] / sc) * sc;
    }
    if (t < 256) { sw1s[t] = g_w1q[t]; sb1s[t] = g_b1q[t]; }
    __syncthreads();

    // weights: 4096 uint4
    #pragma unroll
    for (int i = 0; i < 8; i++) {
        int lin = t + 512 * i;
        int oc = lin >> 5, j = lin & 31;
        uint4 v = ((const uint4*)g_w1cb)[oc * 32 + j];
        *(uint4*)(Ws + oc * 264 + 8 * j) = v;
    }
    // activations: 64 k-words x 256 px
    #pragma unroll
    for (int i = 0; i < 32; i++) {
        int lin = t + 512 * i;                  // 16384
        int k = lin >> 8, px = lin & 255;
        int pglob = p0 + px;
        int b = pglob / HW;
        int s = pglob - b * HW;
        const float* bp = batch + ((size_t)(b * CIN + 4 * k)) * HW + s;
        float f0 = bp[0], f1 = bp[HW], f2 = bp[2 * HW], f3 = bp[3 * HW];
        float4 wv = *(const float4*)&sw1s[4 * k];
        float4 bv = *(const float4*)&sb1s[4 * k];
        float q0 = qclipf(rintf(fmaxf(fmaf(f0, wv.x, bv.x), 0.0f) * inv), 0.0f, 127.0f);
        float q1 = qclipf(rintf(fmaxf(fmaf(f1, wv.y, bv.y), 0.0f) * inv), 0.0f, 127.0f);
        float q2 = qclipf(rintf(fmaxf(fmaf(f2, wv.z, bv.z), 0.0f) * inv), 0.0f, 127.0f);
        float q3 = qclipf(rintf(fmaxf(fmaf(f3, wv.w, bv.w), 0.0f) * inv), 0.0f, 127.0f);
        __nv_bfloat162 h01 = __floats2bfloat162_rn(q0, q1);
        __nv_bfloat162 h23 = __floats2bfloat162_rn(q2, q3);
        uint2 pk;
        pk.x = *(uint32_t*)&h01;
        pk.y = *(uint32_t*)&h23;
        *(uint2*)(Xs + px * 264 + 4 * k) = pk;
    }
    __syncthreads();

    // 16 warps = 4 px-groups(64) x 4 oc-groups(32)
    int wid = t >> 5, l = t & 31;
    int pxg = wid & 3, ocg = wid >> 2;
    uint32_t xs0 = smem_u32(Xs), ws0 = smem_u32(Ws);

    uint32_t aaddr[4], baddr[4];
    #pragma unroll
    for (int mf = 0; mf < 4; mf++)
        aaddr[mf] = xs0 + ((pxg * 64 + mf * 16 + (l & 15)) * 264 + (l >> 4) * 8) * 2;
    #pragma unroll
    for (int nf = 0; nf < 4; nf++)
        baddr[nf] = ws0 + ((ocg * 32 + nf * 8 + (l & 7)) * 264 + ((l >> 3) & 1) * 8) * 2;

    float acc[4][4][4];
    #pragma unroll
    for (int mf = 0; mf < 4; mf++)
        #pragma unroll
        for (int nf = 0; nf < 4; nf++)
            #pragma unroll
            for (int r = 0; r < 4; r++) acc[mf][nf][r] = 0.0f;

    #pragma unroll 2
    for (int ks = 0; ks < 16; ks++) {
        uint32_t a[4][4], bfr[4][2];
        #pragma unroll
        for (int mf = 0; mf < 4; mf++)
            ldsm_x4(a[mf][0], a[mf][1], a[mf][2], a[mf][3], aaddr[mf] + ks * 32);
        #pragma unroll
        for (int nf = 0; nf < 4; nf++)
            ldsm_x2(bfr[nf][0], bfr[nf][1], baddr[nf] + ks * 32);
        #pragma unroll
        for (int mf = 0; mf < 4; mf++)
            #pragma unroll
            for (int nf = 0; nf < 4; nf++)
                mma_bf16(acc[mf][nf], a[mf], bfr[nf]);
    }

    float m = 0.0f;
    #pragma unroll
    for (int mf = 0; mf < 4; mf++) {
        int pxa = p0 + pxg * 64 + mf * 16 + (l >> 2);
        #pragma unroll
        for (int nf = 0; nf < 4; nf++) {
            int oc = ocg * 32 + nf * 8 + (l & 3) * 2;
            float s0 = sc1[oc], s1 = sc1[oc + 1];
            float bb0 = sb1[oc], bb1 = sb1[oc + 1];
            float v0 = fmaxf(fmaf(acc[mf][nf][0], s0, bb0), 0.0f);
            float v1 = fmaxf(fmaf(acc[mf][nf][1], s1, bb1), 0.0f);
            float v2 = fmaxf(fmaf(acc[mf][nf][2], s0, bb0), 0.0f);
            float v3 = fmaxf(fmaf(acc[mf][nf][3], s1, bb1), 0.0f);
            m = fmaxf(m, fmaxf(fmaxf(v0, v1), fmaxf(v2, v3)));
            *(float2*)&g_x2[(size_t)pxa * 128 + oc]       = make_float2(v0, v1);
            *(float2*)&g_x2[(size_t)(pxa + 8) * 128 + oc] = make_float2(v2, v3);
        }
    }
    float bm = blockReduceMax(m);
    if (t == 0) atomicMax(&g_max2, __float_as_uint(bm));
}

// ---------------- K3: quantize x2 (fp32) -> bf16 codes NHWC ----------------
__global__ void k_quant2()
{
    const int n = PX * 32;
    float inv = 1.0f / (__uint_as_float(g_max2) / 127.0f + 1e-8f);
    const float4* xp = (const float4*)g_x2;
    uint2* op = (uint2*)g_x2cb;
    for (int i = blockIdx.x * blockDim.x + threadIdx.x; i < n;
         i += gridDim.x * blockDim.x) {
        float4 v = xp[i];
        float q0 = qclipf(rintf(v.x * inv), 0.0f, 127.0f);
        float q1 = qclipf(rintf(v.y * inv), 0.0f, 127.0f);
        float q2 = qclipf(rintf(v.z * inv), 0.0f, 127.0f);
        float q3 = qclipf(rintf(v.w * inv), 0.0f, 127.0f);
        __nv_bfloat162 h01 = __floats2bfloat162_rn(q0, q1);
        __nv_bfloat162 h23 = __floats2bfloat162_rn(q2, q3);
        uint2 pk;
        pk.x = *(uint32_t*)&h01;
        pk.y = *(uint32_t*)&h23;
        op[i] = pk;
    }
}

// ---- K4: conv2 3x3 via bf16 mma: 9 accumulating GEMMs of K=128 ----
// X smem: [6 rows][58 cols][136 ci-pad] bf16; W smem: [32 oc][1160] bf16.
__global__ __launch_bounds__(256) void k_conv2(float* __restrict__ out)
{
    extern __shared__ __nv_bfloat16 smem2[];
    __nv_bfloat16* Xs  = smem2;                     // 6*58*136 = 47328
    __nv_bfloat16* Wsm = smem2 + 6 * 58 * 136;      // 32*1160 = 37120
    float* scmb = (float*)(Wsm + 32 * 1160);        // 32
    int t = threadIdx.x;
    int h0 = blockIdx.x * 4, b = blockIdx.y;

    float sa2 = __uint_as_float(g_max2) / 127.0f + 1e-8f;
    if (t < 32) scmb[t] = sa2 * g_sw2[t];

    // X staging: 6*58 cells x 16 uint4
    for (int lin = t; lin < 6 * 58 * 16; lin += 256) {
        int cell = lin >> 4, j = lin & 15;
        int row = cell / 58, col = cell - row * 58;
        int hh = h0 + row - 1;
        uint4 v = make_uint4(0, 0, 0, 0);
        if (col >= 1 && col <= 56 && hh >= 0 && hh < 56)
            v = ((const uint4*)(g_x2cb + (size_t)(b * HW + hh * 56 + col - 1) * 128))[j];
        *(uint4*)(Xs + cell * 136 + j * 8) = v;
    }
    // W staging: 32 oc x 144 uint4
    for (int lin = t; lin < 32 * 144; lin += 256) {
        int oc = lin / 144, j = lin - oc * 144;
        ((uint4*)(Wsm + oc * 1160))[j] = ((const uint4*)(g_w2cb + oc * 1160))[j];
    }
    __syncthreads();

    int wid = t >> 5, l = t & 31;
    float m = 0.0f;
    float vv[2][4][4];
    if (wid < 7) {
        uint32_t xs0 = smem_u32(Xs), ws0 = smem_u32(Wsm);
        uint32_t abase[2];
        #pragma unroll
        for (int mf = 0; mf < 2; mf++) {
            int px = wid * 32 + mf * 16 + (l & 15);
            int hl = px / 56, w = px - hl * 56;
            abase[mf] = xs0 + ((hl * 58 + w) * 136 + (l >> 4) * 8) * 2;
        }
        uint32_t bbase[4];
        #pragma unroll
        for (int nf = 0; nf < 4; nf++)
            bbase[nf] = ws0 + ((nf * 8 + (l & 7)) * 1160 + ((l >> 3) & 1) * 8) * 2;

        float acc[2][4][4];
        #pragma unroll
        for (int mf = 0; mf < 2; mf++)
            #pragma unroll
            for (int nf = 0; nf < 4; nf++)
                #pragma unroll
                for (int r = 0; r < 4; r++) acc[mf][nf][r] = 0.0f;

        #pragma unroll 1
        for (int tap = 0; tap < 9; tap++) {
            uint32_t toff = (uint32_t)(((tap / 3) * 58 + (tap % 3)) * 136 * 2);
            uint32_t wtoff = (uint32_t)(tap * 256);
            #pragma unroll
            for (int ks = 0; ks < 8; ks++) {
                uint32_t a[2][4], bfr[4][2];
                ldsm_x4(a[0][0], a[0][1], a[0][2], a[0][3], abase[0] + toff + ks * 32);
                ldsm_x4(a[1][0], a[1][1], a[1][2], a[1][3], abase[1] + toff + ks * 32);
                #pragma unroll
                for (int nf = 0; nf < 4; nf++)
                    ldsm_x2(bfr[nf][0], bfr[nf][1], bbase[nf] + wtoff + ks * 32);
                #pragma unroll
                for (int mf = 0; mf < 2; mf++)
                    #pragma unroll
                    for (int nf = 0; nf < 4; nf++)
                        mma_bf16(acc[mf][nf], a[mf], bfr[nf]);
            }
        }
        // scale, track max
        #pragma unroll
        for (int mf = 0; mf < 2; mf++)
            #pragma unroll
            for (int nf = 0; nf < 4; nf++) {
                int oc = nf * 8 + (l & 3) * 2;
                float s0 = scmb[oc], s1 = scmb[oc + 1];
                vv[mf][nf][0] = acc[mf][nf][0] * s0;
                vv[mf][nf][1] = acc[mf][nf][1] * s1;
                vv[mf][nf][2] = acc[mf][nf][2] * s0;
                vv[mf][nf][3] = acc[mf][nf][3] * s1;
                m = fmaxf(m, fmaxf(fmaxf(fabsf(vv[mf][nf][0]), fabsf(vv[mf][nf][1])),
                                   fmaxf(fabsf(vv[mf][nf][2]), fabsf(vv[mf][nf][3]))));
            }
    }
    __syncthreads();                  // done reading Xs
    float* outs = (float*)Xs;         // [32 oc][228] floats (29.2KB)
    if (wid < 7) {
        #pragma unroll
        for (int mf = 0; mf < 2; mf++) {
            int px = wid * 32 + mf * 16 + (l >> 2);
            #pragma unroll
            for (int nf = 0; nf < 4; nf++) {
                int oc = nf * 8 + (l & 3) * 2;
                outs[oc * 228 + px]           = vv[mf][nf][0];
                outs[(oc + 1) * 228 + px]     = vv[mf][nf][1];
                outs[oc * 228 + px + 8]       = vv[mf][nf][2];
                outs[(oc + 1) * 228 + px + 8] = vv[mf][nf][3];
            }
        }
    }
    __syncthreads();
    size_t obase = ((size_t)b * 288 + 256) * HW + h0 * 56;
    for (int lin = t; lin < 32 * 56; lin += 256) {
        int oc = lin / 56, j = lin - oc * 56;
        float4 v = *(float4*)(outs + oc * 228 + j * 4);
        *(float4*)(out + obase + (size_t)oc * HW + j * 4) = v;
    }
    float bm = blockReduceMax(m);
    if (t == 0) atomicMax(&g_maxy, __float_as_uint(bm));
}

// ------ K5: output requant, plane-per-block (batch, y regions, tail) --------
__global__ __launch_bounds__(256) void k_out(const float4* __restrict__ batch4,
                                             float4* __restrict__ out4,
                                             float* __restrict__ out, int out_size)
{
    int c = blockIdx.x, b = blockIdx.y;
    float s = fmaxf(__uint_as_float(g_maxb), __uint_as_float(g_maxy)) / 127.0f + 1e-8f;
    float inv = 1.0f / s;
    float4* dst = out4 + (b * 288 + c) * HW4;
    if (c < CIN) {
        const float4* src = batch4 + (b * CIN + c) * HW4;
        for (int j = threadIdx.x; j < HW4; j += 256) {
            float4 v = src[j];
            v.x = qclipf(rintf(v.x * inv), -128.0f, 127.0f) * s;
            v.y = qclipf(rintf(v.y * inv), -128.0f, 127.0f) * s;
            v.z = qclipf(rintf(v.z * inv), -128.0f, 127.0f) * s;
            v.w = qclipf(rintf(v.w * inv), -128.0f, 127.0f) * s;
            dst[j] = v;
        }
    } else {
        for (int j = threadIdx.x; j < HW4; j += 256) {
            float4 v = dst[j];
            v.x = qclipf(rintf(v.x * inv), -128.0f, 127.0f) * s;
            v.y = qclipf(rintf(v.y * inv), -128.0f, 127.0f) * s;
            v.z = qclipf(rintf(v.z * inv), -128.0f, 127.0f) * s;
            v.w = qclipf(rintf(v.w * inv), -128.0f, 127.0f) * s;
            dst[j] = v;
        }
    }
    if (c == 0 && b == 0 && threadIdx.x == 0)
        for (int k = N_OUT; k < out_size; k++) out[k] = s;
}

extern "C" void kernel_launch(void* const* d_in, const int* in_sizes, int n_in,
                              void* d_out, int out_size)
{
    const float* batch = (const float*)d_in[0];
    const float* s_in  = (const float*)d_in[1];
    const float* g1    = (const float*)d_in[2];
    const float* be1   = (const float*)d_in[3];
    const float* m1    = (const float*)d_in[4];
    const float* v1    = (const float*)d_in[5];
    const float* w1c   = (const float*)d_in[6];
    const float* g2    = (const float*)d_in[7];
    const float* be2   = (const float*)d_in[8];
    const float* m2    = (const float*)d_in[9];
    const float* v2    = (const float*)d_in[10];
    const float* w2c   = (const float*)d_in[11];
    float* out = (float*)d_out;

    const int CONV1_SMEM = 384 * 264 * 2 + (128 + 128 + 256 + 256) * 4;     // 205824
    const int CONV2_SMEM = (6 * 58 * 136 + 32 * 1160) * 2 + 32 * 4;         // 169024
    static bool attr_done = false;
    if (!attr_done) {
        cudaFuncSetAttribute(k_conv1, cudaFuncAttributeMaxDynamicSharedMemorySize, CONV1_SMEM);
        cudaFuncSetAttribute(k_conv2, cudaFuncAttributeMaxDynamicSharedMemorySize, CONV2_SMEM);
        attr_done = true;
    }

    k_prep1<<<1, 256>>>(g1, be1, m1, v1, s_in);
    k_prep2<<<2, 256>>>(w1c, g2, be2, m2, v2, w2c);
    k_max1<<<dim3(CIN, B_N), 256>>>((const float4*)batch);
    k_conv1<<<PX / 256, 512, CONV1_SMEM>>>(batch);
    k_quant2<<<2048, 256>>>();
    k_conv2<<<dim3(14, 32), 256, CONV2_SMEM>>>(out);
    k_out<<<dim3(288, B_N), 256>>>((const float4*)batch, (float4*)out, out, out_size);
}

// round 8
// speedup vs baseline: 1.1936x; 1.0584x over previous
#include <cuda_runtime.h>
#include <cuda_bf16.h>
#include <cstdint>

#define B_N   32
#define CIN   256
#define HW    3136
#define HW4   784
#define PX    100352          // B_N*HW
#define CO1   128
#define CO2   32
#define N_OUT (32*288*3136)

// ---------------- scratch (device globals; no allocations) ----------------
__device__ float    g_w1q[CIN], g_b1q[CIN];
__device__ float    g_bf[CO1], g_sw1[CO1];
__device__ __nv_bfloat16 g_w1cb[CO1*256];   // conv1 weight codes bf16 [oc][k]
__device__ float    g_sw2[CO2];
__device__ __nv_bfloat16 g_w2cb[CO2*1160];  // conv2 weight codes bf16 [oc][tap*128+ci]
__device__ unsigned g_max1, g_max2, g_maxb, g_maxy;
__device__ float    g_x2[PX*CO1];           // conv1 out fp32 NHWC (51.4MB)

// ---------------- helpers ----------------
__device__ __forceinline__ float warpMax(float v) {
    #pragma unroll
    for (int o = 16; o; o >>= 1) v = fmaxf(v, __shfl_xor_sync(0xffffffffu, v, o));
    return v;
}
__device__ __forceinline__ float blockReduceMax(float v) {
    __shared__ float sm[16];
    float w = warpMax(v);
    if ((threadIdx.x & 31) == 0) sm[threadIdx.x >> 5] = w;
    __syncthreads();
    float r = (threadIdx.x < (blockDim.x >> 5)) ? sm[threadIdx.x] : 0.0f;
    r = warpMax(r);
    __syncthreads();
    return r;  // valid in warp 0
}
__device__ __forceinline__ float qclipf(float q, float lo, float hi) {
    return fminf(fmaxf(q, lo), hi);
}
__device__ __forceinline__ uint32_t smem_u32(const void* p) {
    return (uint32_t)__cvta_generic_to_shared(p);
}
__device__ __forceinline__ void ldsm_x4(uint32_t& r0, uint32_t& r1,
                                        uint32_t& r2, uint32_t& r3, uint32_t a) {
    asm volatile("ldmatrix.sync.aligned.m8n8.x4.shared.b16 {%0,%1,%2,%3}, [%4];"
                 : "=r"(r0), "=r"(r1), "=r"(r2), "=r"(r3) : "r"(a));
}
__device__ __forceinline__ void ldsm_x2(uint32_t& r0, uint32_t& r1, uint32_t a) {
    asm volatile("ldmatrix.sync.aligned.m8n8.x2.shared.b16 {%0,%1}, [%2];"
                 : "=r"(r0), "=r"(r1) : "r"(a));
}
__device__ __forceinline__ void mma_bf16(float* d, const uint32_t* a, const uint32_t* b) {
    asm volatile(
        "mma.sync.aligned.m16n8k16.row.col.f32.bf16.bf16.f32 "
        "{%0,%1,%2,%3},{%4,%5,%6,%7},{%8,%9},{%0,%1,%2,%3};"
        : "+f"(d[0]), "+f"(d[1]), "+f"(d[2]), "+f"(d[3])
        : "r"(a[0]), "r"(a[1]), "r"(a[2]), "r"(a[3]), "r"(b[0]), "r"(b[1]));
}

// ---------------- K0: all weight prep (3 blocks) ----------------
__global__ void k_prep(const float* __restrict__ g1, const float* __restrict__ be1,
                       const float* __restrict__ m1, const float* __restrict__ v1,
                       const float* __restrict__ s_in_p, const float* __restrict__ w1c,
                       const float* __restrict__ g2, const float* __restrict__ be2,
                       const float* __restrict__ m2, const float* __restrict__ v2,
                       const float* __restrict__ w2c)
{
    int t = threadIdx.x;
    if (blockIdx.x == 0) {
        if (t == 0) { g_max1 = 0u; g_max2 = 0u; g_maxb = 0u; g_maxy = 0u; }
        float w1 = g1[t] / sqrtf(v1[t] + 1e-5f);
        float b1 = be1[t] - m1[t] * w1;
        float bm = blockReduceMax(fabsf(w1));
        __shared__ float s_sbn;
        if (t == 0) s_sbn = bm / 127.0f + 1e-8f;
        __syncthreads();
        float sbn = s_sbn;
        float c = qclipf(rintf(w1 / sbn), -128.0f, 127.0f);
        g_w1q[t] = c * sbn;
        float sc = s_in_p[0] * sbn;
        g_b1q[t] = rintf(b1 / sc) * sc;
    } else if (blockIdx.x == 1) {
        if (t < CO1) {
            float tt = g2[t] / sqrtf(v2[t] + 1e-5f);
            const float* wr = w1c + t * CIN;
            float mx = 0.0f;
            for (int c = 0; c < CIN; c++) mx = fmaxf(mx, fabsf(wr[c] * tt));
            float s = mx / 127.0f + 1e-8f;
            g_sw1[t] = s;
            g_bf[t]  = be2[t] - m2[t] * tt;
            for (int c = 0; c < CIN; c++) {
                float code = qclipf(rintf(wr[c] * tt / s), -128.0f, 127.0f);
                g_w1cb[t * 256 + c] = __float2bfloat16(code);   // exact
            }
        }
    } else {
        if (t < CO2) {
            const float* wr = w2c + t * 1152;   // [128 ci][3][3]
            float mx = 0.0f;
            for (int k = 0; k < 1152; k++) mx = fmaxf(mx, fabsf(wr[k]));
            float s = mx / 127.0f + 1e-8f;
            g_sw2[t] = s;
            for (int tap = 0; tap < 9; tap++)
                for (int ci = 0; ci < 128; ci++) {
                    float code = qclipf(rintf(wr[ci * 9 + tap] / s), -128.0f, 127.0f);
                    g_w2cb[t * 1160 + tap * 128 + ci] = __float2bfloat16(code);
                }
        }
    }
}

// ------- K1: max relu(bn1(batch)) and max|batch|, plane-per-block, MLP=4 -----
__global__ __launch_bounds__(256) void k_max1(const float4* __restrict__ batch4)
{
    int ci = blockIdx.x, b = blockIdx.y;
    const float4* p = batch4 + (b * CIN + ci) * HW4;
    float w = g_w1q[ci], bb = g_b1q[ci];
    int t = threadIdx.x;
    float4 v0 = p[t], v1 = p[t + 256], v2 = p[t + 512];
    bool has3 = t < (HW4 - 768);
    float4 v3 = has3 ? p[t + 768] : make_float4(0.0f, 0.0f, 0.0f, 0.0f);
    float m1 = 0.0f, mb = 0.0f;
    #define M1(v) do { \
        m1 = fmaxf(m1, fmaxf(fmaf(v.x, w, bb), 0.0f)); \
        m1 = fmaxf(m1, fmaxf(fmaf(v.y, w, bb), 0.0f)); \
        m1 = fmaxf(m1, fmaxf(fmaf(v.z, w, bb), 0.0f)); \
        m1 = fmaxf(m1, fmaxf(fmaf(v.w, w, bb), 0.0f)); \
        mb = fmaxf(mb, fmaxf(fmaxf(fabsf(v.x), fabsf(v.y)), \
                             fmaxf(fabsf(v.z), fabsf(v.w)))); } while (0)
    M1(v0); M1(v1); M1(v2);
    if (has3) M1(v3);
    #undef M1
    float r1 = blockReduceMax(m1);
    if (t == 0) atomicMax(&g_max1, __float_as_uint(r1));
    float rb = blockReduceMax(mb);
    if (t == 0) atomicMax(&g_maxb, __float_as_uint(rb));
}

// ---- K2: fused bn1+quant + 1x1 conv via bf16 mma (256px x 128oc, K=256) ----
__global__ __launch_bounds__(512) void k_conv1(const float* __restrict__ batch)
{
    extern __shared__ __nv_bfloat16 smemb[];
    __nv_bfloat16* Xs = smemb;                 // [256 px][264]
    __nv_bfloat16* Ws = smemb + 256 * 264;     // [128 oc][264]
    float* sc1  = (float*)(smemb + 384 * 264);
    float* sb1  = sc1 + 128;
    float* sw1s = sb1 + 128;                   // 256
    float* sb1s = sw1s + 256;                  // 256
    int t = threadIdx.x;
    int p0 = blockIdx.x * 256;

    float sa1 = __uint_as_float(g_max1) / 127.0f + 1e-8f;
    float inv = 1.0f / sa1;
    if (t < 128) {
        float sc = sa1 * g_sw1[t];
        sc1[t] = sc;
        sb1[t] = rintf(g_bf[t] / sc) * sc;
    }
    if (t < 256) { sw1s[t] = g_w1q[t]; sb1s[t] = g_b1q[t]; }
    __syncthreads();

    // weights: 4096 uint4
    #pragma unroll
    for (int i = 0; i < 8; i++) {
        int lin = t + 512 * i;
        int oc = lin >> 5, j = lin & 31;
        uint4 v = ((const uint4*)g_w1cb)[oc * 32 + j];
        *(uint4*)(Ws + oc * 264 + 8 * j) = v;
    }
    // activations: 64 k-words x 256 px
    #pragma unroll
    for (int i = 0; i < 32; i++) {
        int lin = t + 512 * i;                  // 16384
        int k = lin >> 8, px = lin & 255;
        int pglob = p0 + px;
        int b = pglob / HW;
        int s = pglob - b * HW;
        const float* bp = batch + ((size_t)(b * CIN + 4 * k)) * HW + s;
        float f0 = bp[0], f1 = bp[HW], f2 = bp[2 * HW], f3 = bp[3 * HW];
        float4 wv = *(const float4*)&sw1s[4 * k];
        float4 bv = *(const float4*)&sb1s[4 * k];
        float q0 = qclipf(rintf(fmaxf(fmaf(f0, wv.x, bv.x), 0.0f) * inv), 0.0f, 127.0f);
        float q1 = qclipf(rintf(fmaxf(fmaf(f1, wv.y, bv.y), 0.0f) * inv), 0.0f, 127.0f);
        float q2 = qclipf(rintf(fmaxf(fmaf(f2, wv.z, bv.z), 0.0f) * inv), 0.0f, 127.0f);
        float q3 = qclipf(rintf(fmaxf(fmaf(f3, wv.w, bv.w), 0.0f) * inv), 0.0f, 127.0f);
        __nv_bfloat162 h01 = __floats2bfloat162_rn(q0, q1);
        __nv_bfloat162 h23 = __floats2bfloat162_rn(q2, q3);
        uint2 pk;
        pk.x = *(uint32_t*)&h01;
        pk.y = *(uint32_t*)&h23;
        *(uint2*)(Xs + px * 264 + 4 * k) = pk;
    }
    __syncthreads();

    // 16 warps = 4 px-groups(64) x 4 oc-groups(32)
    int wid = t >> 5, l = t & 31;
    int pxg = wid & 3, ocg = wid >> 2;
    uint32_t xs0 = smem_u32(Xs), ws0 = smem_u32(Ws);

    uint32_t aaddr[4], baddr[4];
    #pragma unroll
    for (int mf = 0; mf < 4; mf++)
        aaddr[mf] = xs0 + ((pxg * 64 + mf * 16 + (l & 15)) * 264 + (l >> 4) * 8) * 2;
    #pragma unroll
    for (int nf = 0; nf < 4; nf++)
        baddr[nf] = ws0 + ((ocg * 32 + nf * 8 + (l & 7)) * 264 + ((l >> 3) & 1) * 8) * 2;

    float acc[4][4][4];
    #pragma unroll
    for (int mf = 0; mf < 4; mf++)
        #pragma unroll
        for (int nf = 0; nf < 4; nf++)
            #pragma unroll
            for (int r = 0; r < 4; r++) acc[mf][nf][r] = 0.0f;

    #pragma unroll 2
    for (int ks = 0; ks < 16; ks++) {
        uint32_t a[4][4], bfr[4][2];
        #pragma unroll
        for (int mf = 0; mf < 4; mf++)
            ldsm_x4(a[mf][0], a[mf][1], a[mf][2], a[mf][3], aaddr[mf] + ks * 32);
        #pragma unroll
        for (int nf = 0; nf < 4; nf++)
            ldsm_x2(bfr[nf][0], bfr[nf][1], baddr[nf] + ks * 32);
        #pragma unroll
        for (int mf = 0; mf < 4; mf++)
            #pragma unroll
            for (int nf = 0; nf < 4; nf++)
                mma_bf16(acc[mf][nf], a[mf], bfr[nf]);
    }

    float m = 0.0f;
    #pragma unroll
    for (int mf = 0; mf < 4; mf++) {
        int pxa = p0 + pxg * 64 + mf * 16 + (l >> 2);
        #pragma unroll
        for (int nf = 0; nf < 4; nf++) {
            int oc = ocg * 32 + nf * 8 + (l & 3) * 2;
            float s0 = sc1[oc], s1 = sc1[oc + 1];
            float bb0 = sb1[oc], bb1 = sb1[oc + 1];
            float v0 = fmaxf(fmaf(acc[mf][nf][0], s0, bb0), 0.0f);
            float v1 = fmaxf(fmaf(acc[mf][nf][1], s1, bb1), 0.0f);
            float v2 = fmaxf(fmaf(acc[mf][nf][2], s0, bb0), 0.0f);
            float v3 = fmaxf(fmaf(acc[mf][nf][3], s1, bb1), 0.0f);
            m = fmaxf(m, fmaxf(fmaxf(v0, v1), fmaxf(v2, v3)));
            *(float2*)&g_x2[(size_t)pxa * 128 + oc]       = make_float2(v0, v1);
            *(float2*)&g_x2[(size_t)(pxa + 8) * 128 + oc] = make_float2(v2, v3);
        }
    }
    float bm = blockReduceMax(m);
    if (t == 0) atomicMax(&g_max2, __float_as_uint(bm));
}

// ---- K3: conv2 3x3 via bf16 mma, fused x2 quantization in staging ----
// 512 threads, 14 mma warps (one 16px x 32oc tile each), 4 rows x 56 cols.
__global__ __launch_bounds__(512) void k_conv2(float* __restrict__ out)
{
    extern __shared__ __nv_bfloat16 smem2[];
    __nv_bfloat16* Xs  = smem2;                     // [6][58][136] = 47328
    __nv_bfloat16* Wsm = smem2 + 6 * 58 * 136;      // 32*1160 = 37120
    float* scmb = (float*)(Wsm + 32 * 1160);        // 32
    int t = threadIdx.x;
    int h0 = blockIdx.x * 4, b = blockIdx.y;

    float sa2 = __uint_as_float(g_max2) / 127.0f + 1e-8f;
    float inv2 = 1.0f / sa2;
    if (t < 32) scmb[t] = sa2 * g_sw2[t];

    // X staging: read fp32 x2, quantize to bf16 codes (identical math to old k_quant2)
    for (int lin = t; lin < 6 * 58 * 32; lin += 512) {
        int cell = lin >> 5, j = lin & 31;
        int row = cell / 58, col = cell - row * 58;
        int hh = h0 + row - 1;
        float4 v = make_float4(0.0f, 0.0f, 0.0f, 0.0f);
        if (col >= 1 && col <= 56 && hh >= 0 && hh < 56)
            v = ((const float4*)(g_x2 + (size_t)(b * HW + hh * 56 + col - 1) * 128))[j];
        float q0 = qclipf(rintf(v.x * inv2), 0.0f, 127.0f);
        float q1 = qclipf(rintf(v.y * inv2), 0.0f, 127.0f);
        float q2 = qclipf(rintf(v.z * inv2), 0.0f, 127.0f);
        float q3 = qclipf(rintf(v.w * inv2), 0.0f, 127.0f);
        __nv_bfloat162 h01 = __floats2bfloat162_rn(q0, q1);
        __nv_bfloat162 h23 = __floats2bfloat162_rn(q2, q3);
        uint2 pk;
        pk.x = *(uint32_t*)&h01;
        pk.y = *(uint32_t*)&h23;
        *(uint2*)(Xs + cell * 136 + j * 4) = pk;
    }
    // W staging: 32 oc x 144 uint4
    for (int lin = t; lin < 32 * 144; lin += 512) {
        int oc = lin / 144, j = lin - oc * 144;
        ((uint4*)(Wsm + oc * 1160))[j] = ((const uint4*)(g_w2cb + oc * 1160))[j];
    }
    __syncthreads();

    int wid = t >> 5, l = t & 31;
    float m = 0.0f;
    float vv[4][4];
    if (wid < 14) {
        uint32_t xs0 = smem_u32(Xs), ws0 = smem_u32(Wsm);
        int px = wid * 16 + (l & 15);
        int hl = px / 56, w = px - hl * 56;
        uint32_t abase = xs0 + ((hl * 58 + w) * 136 + (l >> 4) * 8) * 2;
        uint32_t bbase[4];
        #pragma unroll
        for (int nf = 0; nf < 4; nf++)
            bbase[nf] = ws0 + ((nf * 8 + (l & 7)) * 1160 + ((l >> 3) & 1) * 8) * 2;

        float acc[4][4];
        #pragma unroll
        for (int nf = 0; nf < 4; nf++)
            #pragma unroll
            for (int r = 0; r < 4; r++) acc[nf][r] = 0.0f;

        #pragma unroll 1
        for (int tap = 0; tap < 9; tap++) {
            uint32_t toff = (uint32_t)(((tap / 3) * 58 + (tap % 3)) * 136 * 2);
            uint32_t wtoff = (uint32_t)(tap * 256);
            #pragma unroll
            for (int ks = 0; ks < 8; ks++) {
                uint32_t a[4], bfr[4][2];
                ldsm_x4(a[0], a[1], a[2], a[3], abase + toff + ks * 32);
                #pragma unroll
                for (int nf = 0; nf < 4; nf++)
                    ldsm_x2(bfr[nf][0], bfr[nf][1], bbase[nf] + wtoff + ks * 32);
                #pragma unroll
                for (int nf = 0; nf < 4; nf++)
                    mma_bf16(acc[nf], a, bfr[nf]);
            }
        }
        #pragma unroll
        for (int nf = 0; nf < 4; nf++) {
            int oc = nf * 8 + (l & 3) * 2;
            float s0 = scmb[oc], s1 = scmb[oc + 1];
            vv[nf][0] = acc[nf][0] * s0;
            vv[nf][1] = acc[nf][1] * s1;
            vv[nf][2] = acc[nf][2] * s0;
            vv[nf][3] = acc[nf][3] * s1;
            m = fmaxf(m, fmaxf(fmaxf(fabsf(vv[nf][0]), fabsf(vv[nf][1])),
                               fmaxf(fabsf(vv[nf][2]), fabsf(vv[nf][3]))));
        }
    }
    __syncthreads();                  // done reading Xs
    float* outs = (float*)Xs;         // [32 oc][228] floats
    if (wid < 14) {
        int px = wid * 16 + (l >> 2);
        #pragma unroll
        for (int nf = 0; nf < 4; nf++) {
            int oc = nf * 8 + (l & 3) * 2;
            outs[oc * 228 + px]           = vv[nf][0];
            outs[(oc + 1) * 228 + px]     = vv[nf][1];
            outs[oc * 228 + px + 8]       = vv[nf][2];
            outs[(oc + 1) * 228 + px + 8] = vv[nf][3];
        }
    }
    __syncthreads();
    size_t obase = ((size_t)b * 288 + 256) * HW + h0 * 56;
    for (int lin = t; lin < 32 * 56; lin += 512) {
        int oc = lin / 56, j = lin - oc * 56;
        float4 v = *(float4*)(outs + oc * 228 + j * 4);
        *(float4*)(out + obase + (size_t)oc * HW + j * 4) = v;
    }
    float bm = blockReduceMax(m);
    if (t == 0) atomicMax(&g_maxy, __float_as_uint(bm));
}

// ------ K4: output requant, plane-per-block, MLP=4 --------
__global__ __launch_bounds__(256) void k_out(const float4* __restrict__ batch4,
                                             float4* __restrict__ out4,
                                             float* __restrict__ out, int out_size)
{
    int c = blockIdx.x, b = blockIdx.y;
    float s = fmaxf(__uint_as_float(g_maxb), __uint_as_float(g_maxy)) / 127.0f + 1e-8f;
    float inv = 1.0f / s;
    int t = threadIdx.x;
    float4* dst = out4 + (b * 288 + c) * HW4;
    const float4* src = (c < CIN) ? (batch4 + (b * CIN + c) * HW4) : dst;
    float4 v0 = src[t], v1 = src[t + 256], v2 = src[t + 512];
    bool has3 = t < (HW4 - 768);
    float4 v3 = has3 ? src[t + 768] : make_float4(0.0f, 0.0f, 0.0f, 0.0f);
    #define RQ(v) do { \
        v.x = qclipf(rintf(v.x * inv), -128.0f, 127.0f) * s; \
        v.y = qclipf(rintf(v.y * inv), -128.0f, 127.0f) * s; \
        v.z = qclipf(rintf(v.z * inv), -128.0f, 127.0f) * s; \
        v.w = qclipf(rintf(v.w * inv), -128.0f, 127.0f) * s; } while (0)
    RQ(v0); RQ(v1); RQ(v2);
    dst[t] = v0; dst[t + 256] = v1; dst[t + 512] = v2;
    if (has3) { RQ(v3); dst[t + 768] = v3; }
    #undef RQ
    if (c == 0 && b == 0 && t == 0)
        for (int k = N_OUT; k < out_size; k++) out[k] = s;
}

extern "C" void kernel_launch(void* const* d_in, const int* in_sizes, int n_in,
                              void* d_out, int out_size)
{
    const float* batch = (const float*)d_in[0];
    const float* s_in  = (const float*)d_in[1];
    const float* g1    = (const float*)d_in[2];
    const float* be1   = (const float*)d_in[3];
    const float* m1    = (const float*)d_in[4];
    const float* v1    = (const float*)d_in[5];
    const float* w1c   = (const float*)d_in[6];
    const float* g2    = (const float*)d_in[7];
    const float* be2   = (const float*)d_in[8];
    const float* m2    = (const float*)d_in[9];
    const float* v2    = (const float*)d_in[10];
    const float* w2c   = (const float*)d_in[11];
    float* out = (float*)d_out;

    const int CONV1_SMEM = 384 * 264 * 2 + (128 + 128 + 256 + 256) * 4;     // 205824
    const int CONV2_SMEM = (6 * 58 * 136 + 32 * 1160) * 2 + 32 * 4;         // 169024
    static bool attr_done = false;
    if (!attr_done) {
        cudaFuncSetAttribute(k_conv1, cudaFuncAttributeMaxDynamicSharedMemorySize, CONV1_SMEM);
        cudaFuncSetAttribute(k_conv2, cudaFuncAttributeMaxDynamicSharedMemorySize, CONV2_SMEM);
        attr_done = true;
    }

    k_prep<<<3, 256>>>(g1, be1, m1, v1, s_in, w1c, g2, be2, m2, v2, w2c);  // 0
    k_max1<<<dim3(CIN, B_N), 256>>>((const float4*)batch);                 // 1
    k_conv1<<<PX / 256, 512, CONV1_SMEM>>>(batch);                         // 2
    k_conv2<<<dim3(14, 32), 512, CONV2_SMEM>>>(out);                       // 3 (profiled)
    k_out<<<dim3(288, B_N), 256>>>((const float4*)batch, (float4*)out, out, out_size);
}

// round 9
// speedup vs baseline: 2.0900x; 1.7510x over previous
#include <cuda_runtime.h>
#include <cuda_bf16.h>
#include <cstdint>

#define B_N   32
#define CIN   256
#define HW    3136
#define HW4   784
#define PX    100352          // B_N*HW
#define CO1   128
#define CO2   32
#define N_OUT (32*288*3136)

// ---------------- scratch (device globals; no allocations) ----------------
__device__ float    g_w1q[CIN], g_b1q[CIN];
__device__ float    g_bf[CO1], g_sw1[CO1];
__device__ __nv_bfloat16 g_w1cb[CO1*256];   // conv1 weight codes bf16 [oc][k]
__device__ float    g_sw2[CO2];
__device__ __nv_bfloat16 g_w2cb[CO2*1160];  // conv2 weight codes bf16 [oc][tap*128+ci]
__device__ unsigned g_max1, g_max2, g_maxb, g_maxy;
__device__ float    g_x2[PX*CO1];           // conv1 out fp32 NHWC (51.4MB)

// ---------------- helpers ----------------
__device__ __forceinline__ float warpMax(float v) {
    #pragma unroll
    for (int o = 16; o; o >>= 1) v = fmaxf(v, __shfl_xor_sync(0xffffffffu, v, o));
    return v;
}
__device__ __forceinline__ float blockReduceMax(float v) {
    __shared__ float sm[16];
    float w = warpMax(v);
    if ((threadIdx.x & 31) == 0) sm[threadIdx.x >> 5] = w;
    __syncthreads();
    float r = (threadIdx.x < (blockDim.x >> 5)) ? sm[threadIdx.x] : 0.0f;
    r = warpMax(r);
    __syncthreads();
    return r;  // valid in warp 0
}
__device__ __forceinline__ float qclipf(float q, float lo, float hi) {
    return fminf(fmaxf(q, lo), hi);
}
__device__ __forceinline__ uint32_t smem_u32(const void* p) {
    return (uint32_t)__cvta_generic_to_shared(p);
}
__device__ __forceinline__ void ldsm_x4(uint32_t& r0, uint32_t& r1,
                                        uint32_t& r2, uint32_t& r3, uint32_t a) {
    asm volatile("ldmatrix.sync.aligned.m8n8.x4.shared.b16 {%0,%1,%2,%3}, [%4];"
                 : "=r"(r0), "=r"(r1), "=r"(r2), "=r"(r3) : "r"(a));
}
__device__ __forceinline__ void ldsm_x2(uint32_t& r0, uint32_t& r1, uint32_t a) {
    asm volatile("ldmatrix.sync.aligned.m8n8.x2.shared.b16 {%0,%1}, [%2];"
                 : "=r"(r0), "=r"(r1) : "r"(a));
}
__device__ __forceinline__ void mma_bf16(float* d, const uint32_t* a, const uint32_t* b) {
    asm volatile(
        "mma.sync.aligned.m16n8k16.row.col.f32.bf16.bf16.f32 "
        "{%0,%1,%2,%3},{%4,%5,%6,%7},{%8,%9},{%0,%1,%2,%3};"
        : "+f"(d[0]), "+f"(d[1]), "+f"(d[2]), "+f"(d[3])
        : "r"(a[0]), "r"(a[1]), "r"(a[2]), "r"(a[3]), "r"(b[0]), "r"(b[1]));
}

// ---------------- K0: all weight prep (3 blocks, warp-parallel) ----------------
__global__ void k_prep(const float* __restrict__ g1, const float* __restrict__ be1,
                       const float* __restrict__ m1, const float* __restrict__ v1,
                       const float* __restrict__ s_in_p, const float* __restrict__ w1c,
                       const float* __restrict__ g2, const float* __restrict__ be2,
                       const float* __restrict__ m2, const float* __restrict__ v2,
                       const float* __restrict__ w2c)
{
    int t = threadIdx.x;
    int w = t >> 5, l = t & 31;
    if (blockIdx.x == 0) {
        if (t == 0) { g_max1 = 0u; g_max2 = 0u; g_maxb = 0u; g_maxy = 0u; }
        float w1 = g1[t] / sqrtf(v1[t] + 1e-5f);
        float b1 = be1[t] - m1[t] * w1;
        float bm = blockReduceMax(fabsf(w1));
        __shared__ float s_sbn;
        if (t == 0) s_sbn = bm / 127.0f + 1e-8f;
        __syncthreads();
        float sbn = s_sbn;
        float c = qclipf(rintf(w1 / sbn), -128.0f, 127.0f);
        g_w1q[t] = c * sbn;
        float sc = s_in_p[0] * sbn;
        g_b1q[t] = rintf(b1 / sc) * sc;
    } else if (blockIdx.x == 1) {
        // conv1 weights: warp per oc (16 oc per warp)
        for (int o = w; o < CO1; o += 8) {
            float tt = g2[o] / sqrtf(v2[o] + 1e-5f);
            const float* wr = w1c + o * CIN;
            float mx = 0.0f;
            #pragma unroll
            for (int i = 0; i < 8; i++) mx = fmaxf(mx, fabsf(wr[l + 32 * i] * tt));
            mx = warpMax(mx);
            float s = mx / 127.0f + 1e-8f;
            if (l == 0) { g_sw1[o] = s; g_bf[o] = be2[o] - m2[o] * tt; }
            #pragma unroll
            for (int i = 0; i < 8; i++) {
                int c = l + 32 * i;
                float code = qclipf(rintf(wr[c] * tt / s), -128.0f, 127.0f);
                g_w1cb[o * 256 + c] = __float2bfloat16(code);
            }
        }
    } else {
        // conv2 weights: warp per oc (4 oc per warp)
        for (int o = w; o < CO2; o += 8) {
            const float* wr = w2c + o * 1152;
            float mx = 0.0f;
            #pragma unroll
            for (int i = 0; i < 36; i++) mx = fmaxf(mx, fabsf(wr[l + 32 * i]));
            mx = warpMax(mx);
            float s = mx / 127.0f + 1e-8f;
            if (l == 0) g_sw2[o] = s;
            #pragma unroll
            for (int i = 0; i < 36; i++) {
                int j = l + 32 * i;
                int tap = j >> 7, ci = j & 127;
                float code = qclipf(rintf(wr[ci * 9 + tap] / s), -128.0f, 127.0f);
                g_w2cb[o * 1160 + j] = __float2bfloat16(code);
            }
        }
    }
}

// ------- K1: max relu(bn1(batch)) and max|batch|, plane-per-block, MLP=4 -----
__global__ __launch_bounds__(256) void k_max1(const float4* __restrict__ batch4)
{
    int ci = blockIdx.x, b = blockIdx.y;
    const float4* p = batch4 + (b * CIN + ci) * HW4;
    float w = g_w1q[ci], bb = g_b1q[ci];
    int t = threadIdx.x;
    float4 v0 = p[t], v1 = p[t + 256], v2 = p[t + 512];
    bool has3 = t < (HW4 - 768);
    float4 v3 = has3 ? p[t + 768] : make_float4(0.0f, 0.0f, 0.0f, 0.0f);
    float m1 = 0.0f, mb = 0.0f;
    #define M1(v) do { \
        m1 = fmaxf(m1, fmaxf(fmaf(v.x, w, bb), 0.0f)); \
        m1 = fmaxf(m1, fmaxf(fmaf(v.y, w, bb), 0.0f)); \
        m1 = fmaxf(m1, fmaxf(fmaf(v.z, w, bb), 0.0f)); \
        m1 = fmaxf(m1, fmaxf(fmaf(v.w, w, bb), 0.0f)); \
        mb = fmaxf(mb, fmaxf(fmaxf(fabsf(v.x), fabsf(v.y)), \
                             fmaxf(fabsf(v.z), fabsf(v.w)))); } while (0)
    M1(v0); M1(v1); M1(v2);
    if (has3) M1(v3);
    #undef M1
    float r1 = blockReduceMax(m1);
    if (t == 0) atomicMax(&g_max1, __float_as_uint(r1));
    float rb = blockReduceMax(mb);
    if (t == 0) atomicMax(&g_maxb, __float_as_uint(rb));
}

// ---- K2: fused bn1+quant + 1x1 conv via bf16 mma (128px x 128oc, K=256) ----
// W double-buffered in 4 chunks of 64 ci -> 107.5KB smem -> 2 CTA/SM.
__global__ __launch_bounds__(256, 2) void k_conv1(const float* __restrict__ batch)
{
    extern __shared__ __nv_bfloat16 smemb[];
    __nv_bfloat16* Xs = smemb;                          // [128 px][264]
    __nv_bfloat16* Wb = smemb + 128 * 264;              // [2][128 oc][72]
    float* sc1  = (float*)(smemb + 128 * 264 + 2 * 128 * 72);
    float* sb1  = sc1 + 128;
    float* sw1s = sb1 + 128;                            // 256
    float* sb1s = sw1s + 256;                           // 256
    int t = threadIdx.x;
    int p0 = blockIdx.x * 128;

    float sa1 = __uint_as_float(g_max1) / 127.0f + 1e-8f;
    float inv = 1.0f / sa1;
    if (t < 128) {
        float sc = sa1 * g_sw1[t];
        sc1[t] = sc;
        sb1[t] = rintf(g_bf[t] / sc) * sc;
    }
    sw1s[t] = g_w1q[t];
    sb1s[t] = g_b1q[t];
    __syncthreads();

    // X staging: 8192 = 64 kwords x 128 px
    #pragma unroll
    for (int i = 0; i < 32; i++) {
        int lin = t + 256 * i;
        int k = lin >> 7, px = lin & 127;
        int pglob = p0 + px;
        int b = pglob / HW;
        int s = pglob - b * HW;
        const float* bp = batch + ((size_t)(b * CIN + 4 * k)) * HW + s;
        float f0 = bp[0], f1 = bp[HW], f2 = bp[2 * HW], f3 = bp[3 * HW];
        float4 wv = *(const float4*)&sw1s[4 * k];
        float4 bv = *(const float4*)&sb1s[4 * k];
        float q0 = qclipf(rintf(fmaxf(fmaf(f0, wv.x, bv.x), 0.0f) * inv), 0.0f, 127.0f);
        float q1 = qclipf(rintf(fmaxf(fmaf(f1, wv.y, bv.y), 0.0f) * inv), 0.0f, 127.0f);
        float q2 = qclipf(rintf(fmaxf(fmaf(f2, wv.z, bv.z), 0.0f) * inv), 0.0f, 127.0f);
        float q3 = qclipf(rintf(fmaxf(fmaf(f3, wv.w, bv.w), 0.0f) * inv), 0.0f, 127.0f);
        __nv_bfloat162 h01 = __floats2bfloat162_rn(q0, q1);
        __nv_bfloat162 h23 = __floats2bfloat162_rn(q2, q3);
        uint2 pk;
        pk.x = *(uint32_t*)&h01;
        pk.y = *(uint32_t*)&h23;
        *(uint2*)(Xs + px * 264 + 4 * k) = pk;
    }
    // W chunk 0: 1024 uint4
    #pragma unroll
    for (int i = 0; i < 4; i++) {
        int lin = t + 256 * i;
        int oc = lin >> 3, j = lin & 7;
        *(uint4*)(Wb + oc * 72 + j * 8) = ((const uint4*)(g_w1cb + oc * 256))[j];
    }
    __syncthreads();

    // 8 warps = 2 px-groups(64) x 4 oc-groups(32)
    int wid = t >> 5, l = t & 31;
    int pxg = wid & 1, ocg = wid >> 1;
    uint32_t xs0 = smem_u32(Xs), wb0 = smem_u32(Wb);

    uint32_t aaddr[4], boff[4];
    #pragma unroll
    for (int mf = 0; mf < 4; mf++)
        aaddr[mf] = xs0 + ((pxg * 64 + mf * 16 + (l & 15)) * 264 + (l >> 4) * 8) * 2;
    #pragma unroll
    for (int nf = 0; nf < 4; nf++)
        boff[nf] = ((ocg * 32 + nf * 8 + (l & 7)) * 72 + ((l >> 3) & 1) * 8) * 2;

    float acc[4][4][4];
    #pragma unroll
    for (int mf = 0; mf < 4; mf++)
        #pragma unroll
        for (int nf = 0; nf < 4; nf++)
            #pragma unroll
            for (int r = 0; r < 4; r++) acc[mf][nf][r] = 0.0f;

    #pragma unroll 1
    for (int c = 0; c < 4; c++) {
        if (c < 3) {
            int p1 = (c + 1) & 1;
            #pragma unroll
            for (int i = 0; i < 4; i++) {
                int lin = t + 256 * i;
                int oc = lin >> 3, j = lin & 7;
                *(uint4*)(Wb + p1 * 128 * 72 + oc * 72 + j * 8) =
                    ((const uint4*)(g_w1cb + oc * 256 + (c + 1) * 64))[j];
            }
        }
        uint32_t wbp = wb0 + (uint32_t)((c & 1) * 128 * 72 * 2);
        #pragma unroll
        for (int ksl = 0; ksl < 4; ksl++) {
            int ks = c * 4 + ksl;
            uint32_t a[4][4], bfr[4][2];
            #pragma unroll
            for (int mf = 0; mf < 4; mf++)
                ldsm_x4(a[mf][0], a[mf][1], a[mf][2], a[mf][3], aaddr[mf] + ks * 32);
            #pragma unroll
            for (int nf = 0; nf < 4; nf++)
                ldsm_x2(bfr[nf][0], bfr[nf][1], wbp + boff[nf] + ksl * 32);
            #pragma unroll
            for (int mf = 0; mf < 4; mf++)
                #pragma unroll
                for (int nf = 0; nf < 4; nf++)
                    mma_bf16(acc[mf][nf], a[mf], bfr[nf]);
        }
        __syncthreads();
    }

    float m = 0.0f;
    #pragma unroll
    for (int mf = 0; mf < 4; mf++) {
        int pxa = p0 + pxg * 64 + mf * 16 + (l >> 2);
        #pragma unroll
        for (int nf = 0; nf < 4; nf++) {
            int oc = ocg * 32 + nf * 8 + (l & 3) * 2;
            float s0 = sc1[oc], s1 = sc1[oc + 1];
            float bb0 = sb1[oc], bb1 = sb1[oc + 1];
            float v0 = fmaxf(fmaf(acc[mf][nf][0], s0, bb0), 0.0f);
            float v1 = fmaxf(fmaf(acc[mf][nf][1], s1, bb1), 0.0f);
            float v2 = fmaxf(fmaf(acc[mf][nf][2], s0, bb0), 0.0f);
            float v3 = fmaxf(fmaf(acc[mf][nf][3], s1, bb1), 0.0f);
            m = fmaxf(m, fmaxf(fmaxf(v0, v1), fmaxf(v2, v3)));
            *(float2*)&g_x2[(size_t)pxa * 128 + oc]       = make_float2(v0, v1);
            *(float2*)&g_x2[(size_t)(pxa + 8) * 128 + oc] = make_float2(v2, v3);
        }
    }
    float bm = blockReduceMax(m);
    if (t == 0) atomicMax(&g_max2, __float_as_uint(bm));
}

// ---- K3: conv2 3x3 via bf16 mma, fused quant, per-tap W double buffer ----
// smem 112.2KB -> 2 CTA/SM. 512 threads, 14 mma warps.
__global__ __launch_bounds__(512, 2) void k_conv2(float* __restrict__ out)
{
    extern __shared__ __nv_bfloat16 smem2[];
    __nv_bfloat16* Xs = smem2;                          // [6][58][136] = 47328
    __nv_bfloat16* Wb = smem2 + 6 * 58 * 136;           // [2][32 oc][136]
    float* scmb = (float*)(Wb + 2 * 32 * 136);          // 32
    int t = threadIdx.x;
    int h0 = blockIdx.x * 4, b = blockIdx.y;

    float sa2 = __uint_as_float(g_max2) / 127.0f + 1e-8f;
    float inv2 = 1.0f / sa2;
    if (t < 32) scmb[t] = sa2 * g_sw2[t];

    // X staging with fused quantization (identical math to reference path)
    for (int lin = t; lin < 6 * 58 * 32; lin += 512) {
        int cell = lin >> 5, j = lin & 31;
        int row = cell / 58, col = cell - row * 58;
        int hh = h0 + row - 1;
        float4 v = make_float4(0.0f, 0.0f, 0.0f, 0.0f);
        if (col >= 1 && col <= 56 && hh >= 0 && hh < 56)
            v = ((const float4*)(g_x2 + (size_t)(b * HW + hh * 56 + col - 1) * 128))[j];
        float q0 = qclipf(rintf(v.x * inv2), 0.0f, 127.0f);
        float q1 = qclipf(rintf(v.y * inv2), 0.0f, 127.0f);
        float q2 = qclipf(rintf(v.z * inv2), 0.0f, 127.0f);
        float q3 = qclipf(rintf(v.w * inv2), 0.0f, 127.0f);
        __nv_bfloat162 h01 = __floats2bfloat162_rn(q0, q1);
        __nv_bfloat162 h23 = __floats2bfloat162_rn(q2, q3);
        uint2 pk;
        pk.x = *(uint32_t*)&h01;
        pk.y = *(uint32_t*)&h23;
        *(uint2*)(Xs + cell * 136 + j * 4) = pk;
    }
    // W tap 0: 512 uint4, one per thread
    {
        int oc = t >> 4, j = t & 15;
        *(uint4*)(Wb + oc * 136 + j * 8) = ((const uint4*)(g_w2cb + oc * 1160))[j];
    }
    __syncthreads();

    int wid = t >> 5, l = t & 31;
    float m = 0.0f;
    float vv[4][4];
    uint32_t xs0 = smem_u32(Xs), wb0 = smem_u32(Wb);
    int px = wid * 16 + (l & 15);
    int hl = px / 56, ww = px - hl * 56;
    uint32_t abase = xs0 + ((hl * 58 + ww) * 136 + (l >> 4) * 8) * 2;
    uint32_t boff[4];
    #pragma unroll
    for (int nf = 0; nf < 4; nf++)
        boff[nf] = ((nf * 8 + (l & 7)) * 136 + ((l >> 3) & 1) * 8) * 2;

    float acc[4][4];
    #pragma unroll
    for (int nf = 0; nf < 4; nf++)
        #pragma unroll
        for (int r = 0; r < 4; r++) acc[nf][r] = 0.0f;

    #pragma unroll 1
    for (int tap = 0; tap < 9; tap++) {
        if (tap < 8) {
            int p1 = (tap + 1) & 1;
            int oc = t >> 4, j = t & 15;
            *(uint4*)(Wb + p1 * 32 * 136 + oc * 136 + j * 8) =
                ((const uint4*)(g_w2cb + oc * 1160 + (tap + 1) * 128))[j];
        }
        if (wid < 14) {
            uint32_t toff = (uint32_t)(((tap / 3) * 58 + (tap % 3)) * 136 * 2);
            uint32_t wbp = wb0 + (uint32_t)((tap & 1) * 32 * 136 * 2);
            #pragma unroll
            for (int ks = 0; ks < 8; ks++) {
                uint32_t a[4], bfr[4][2];
                ldsm_x4(a[0], a[1], a[2], a[3], abase + toff + ks * 32);
                #pragma unroll
                for (int nf = 0; nf < 4; nf++)
                    ldsm_x2(bfr[nf][0], bfr[nf][1], wbp + boff[nf] + ks * 32);
                #pragma unroll
                for (int nf = 0; nf < 4; nf++)
                    mma_bf16(acc[nf], a, bfr[nf]);
            }
        }
        __syncthreads();
    }
    if (wid < 14) {
        #pragma unroll
        for (int nf = 0; nf < 4; nf++) {
            int oc = nf * 8 + (l & 3) * 2;
            float s0 = scmb[oc], s1 = scmb[oc + 1];
            vv[nf][0] = acc[nf][0] * s0;
            vv[nf][1] = acc[nf][1] * s1;
            vv[nf][2] = acc[nf][2] * s0;
            vv[nf][3] = acc[nf][3] * s1;
            m = fmaxf(m, fmaxf(fmaxf(fabsf(vv[nf][0]), fabsf(vv[nf][1])),
                               fmaxf(fabsf(vv[nf][2]), fabsf(vv[nf][3]))));
        }
    }
    __syncthreads();                  // done reading Xs
    float* outs = (float*)Xs;         // [32 oc][228] floats
    if (wid < 14) {
        int pxo = wid * 16 + (l >> 2);
        #pragma unroll
        for (int nf = 0; nf < 4; nf++) {
            int oc = nf * 8 + (l & 3) * 2;
            outs[oc * 228 + pxo]           = vv[nf][0];
            outs[(oc + 1) * 228 + pxo]     = vv[nf][1];
            outs[oc * 228 + pxo + 8]       = vv[nf][2];
            outs[(oc + 1) * 228 + pxo + 8] = vv[nf][3];
        }
    }
    __syncthreads();
    size_t obase = ((size_t)b * 288 + 256) * HW + h0 * 56;
    for (int lin = t; lin < 32 * 56; lin += 512) {
        int oc = lin / 56, j = lin - oc * 56;
        float4 v = *(float4*)(outs + oc * 228 + j * 4);
        *(float4*)(out + obase + (size_t)oc * HW + j * 4) = v;
    }
    float bm = blockReduceMax(m);
    if (t == 0) atomicMax(&g_maxy, __float_as_uint(bm));
}

// ------ K4: output requant, plane-per-block, MLP=4 --------
__global__ __launch_bounds__(256) void k_out(const float4* __restrict__ batch4,
                                             float4* __restrict__ out4,
                                             float* __restrict__ out, int out_size)
{
    int c = blockIdx.x, b = blockIdx.y;
    float s = fmaxf(__uint_as_float(g_maxb), __uint_as_float(g_maxy)) / 127.0f + 1e-8f;
    float inv = 1.0f / s;
    int t = threadIdx.x;
    float4* dst = out4 + (b * 288 + c) * HW4;
    const float4* src = (c < CIN) ? (batch4 + (b * CIN + c) * HW4) : dst;
    float4 v0 = src[t], v1 = src[t + 256], v2 = src[t + 512];
    bool has3 = t < (HW4 - 768);
    float4 v3 = has3 ? src[t + 768] : make_float4(0.0f, 0.0f, 0.0f, 0.0f);
    #define RQ(v) do { \
        v.x = qclipf(rintf(v.x * inv), -128.0f, 127.0f) * s; \
        v.y = qclipf(rintf(v.y * inv), -128.0f, 127.0f) * s; \
        v.z = qclipf(rintf(v.z * inv), -128.0f, 127.0f) * s; \
        v.w = qclipf(rintf(v.w * inv), -128.0f, 127.0f) * s; } while (0)
    RQ(v0); RQ(v1); RQ(v2);
    dst[t] = v0; dst[t + 256] = v1; dst[t + 512] = v2;
    if (has3) { RQ(v3); dst[t + 768] = v3; }
    #undef RQ
    if (c == 0 && b == 0 && t == 0)
        for (int k = N_OUT; k < out_size; k++) out[k] = s;
}

extern "C" void kernel_launch(void* const* d_in, const int* in_sizes, int n_in,
                              void* d_out, int out_size)
{
    const float* batch = (const float*)d_in[0];
    const float* s_in  = (const float*)d_in[1];
    const float* g1    = (const float*)d_in[2];
    const float* be1   = (const float*)d_in[3];
    const float* m1    = (const float*)d_in[4];
    const float* v1    = (const float*)d_in[5];
    const float* w1c   = (const float*)d_in[6];
    const float* g2    = (const float*)d_in[7];
    const float* be2   = (const float*)d_in[8];
    const float* m2    = (const float*)d_in[9];
    const float* v2    = (const float*)d_in[10];
    const float* w2c   = (const float*)d_in[11];
    float* out = (float*)d_out;

    const int CONV1_SMEM = 128 * 264 * 2 + 2 * 128 * 72 * 2
                         + (128 + 128 + 256 + 256) * 4;                 // 107520
    const int CONV2_SMEM = (6 * 58 * 136 + 2 * 32 * 136) * 2 + 32 * 4;  // 112192
    static bool attr_done = false;
    if (!attr_done) {
        cudaFuncSetAttribute(k_conv1, cudaFuncAttributeMaxDynamicSharedMemorySize, CONV1_SMEM);
        cudaFuncSetAttribute(k_conv2, cudaFuncAttributeMaxDynamicSharedMemorySize, CONV2_SMEM);
        attr_done = true;
    }

    k_prep<<<3, 256>>>(g1, be1, m1, v1, s_in, w1c, g2, be2, m2, v2, w2c);  // 0
    k_max1<<<dim3(CIN, B_N), 256>>>((const float4*)batch);                 // 1
    k_conv1<<<PX / 128, 256, CONV1_SMEM>>>(batch);                         // 2
    k_conv2<<<dim3(14, 32), 512, CONV2_SMEM>>>(out);                       // 3 (profiled)
    k_out<<<dim3(288, B_N), 256>>>((const float4*)batch, (float4*)out, out, out_size);
}

// round 10
// speedup vs baseline: 2.0974x; 1.0035x over previous
#include <cuda_runtime.h>
#include <cuda_bf16.h>
#include <cstdint>

#define B_N   32
#define CIN   256
#define HW    3136
#define HW4   784
#define PX    100352          // B_N*HW
#define CO1   128
#define CO2   32
#define N_OUT (32*288*3136)

// ---------------- scratch (device globals; no allocations) ----------------
__device__ float    g_w1q[CIN], g_b1q[CIN];
__device__ float    g_bf[CO1], g_sw1[CO1];
__device__ __nv_bfloat16 g_w1cb[CO1*256];   // conv1 weight codes bf16 [oc][k]
__device__ float    g_sw2[CO2];
__device__ __nv_bfloat16 g_w2cb[CO2*1160];  // conv2 weight codes bf16 [oc][tap*128+ci]
__device__ unsigned g_max1, g_max2, g_maxb, g_maxy;
__device__ float    g_x2[PX*CO1];           // conv1 out fp32 NHWC (51.4MB)

// ---------------- helpers ----------------
__device__ __forceinline__ float warpMax(float v) {
    #pragma unroll
    for (int o = 16; o; o >>= 1) v = fmaxf(v, __shfl_xor_sync(0xffffffffu, v, o));
    return v;
}
__device__ __forceinline__ float blockReduceMax(float v) {
    __shared__ float sm[16];
    float w = warpMax(v);
    if ((threadIdx.x & 31) == 0) sm[threadIdx.x >> 5] = w;
    __syncthreads();
    float r = (threadIdx.x < (blockDim.x >> 5)) ? sm[threadIdx.x] : 0.0f;
    r = warpMax(r);
    __syncthreads();
    return r;  // valid in warp 0
}
__device__ __forceinline__ float qclipf(float q, float lo, float hi) {
    return fminf(fmaxf(q, lo), hi);
}
__device__ __forceinline__ uint32_t smem_u32(const void* p) {
    return (uint32_t)__cvta_generic_to_shared(p);
}
__device__ __forceinline__ void ldsm_x4(uint32_t& r0, uint32_t& r1,
                                        uint32_t& r2, uint32_t& r3, uint32_t a) {
    asm volatile("ldmatrix.sync.aligned.m8n8.x4.shared.b16 {%0,%1,%2,%3}, [%4];"
                 : "=r"(r0), "=r"(r1), "=r"(r2), "=r"(r3) : "r"(a));
}
__device__ __forceinline__ void mma_bf16(float* d, const uint32_t* a, const uint32_t* b) {
    asm volatile(
        "mma.sync.aligned.m16n8k16.row.col.f32.bf16.bf16.f32 "
        "{%0,%1,%2,%3},{%4,%5,%6,%7},{%8,%9},{%0,%1,%2,%3};"
        : "+f"(d[0]), "+f"(d[1]), "+f"(d[2]), "+f"(d[3])
        : "r"(a[0]), "r"(a[1]), "r"(a[2]), "r"(a[3]), "r"(b[0]), "r"(b[1]));
}

// ---------------- K0: all weight prep (3 blocks, warp-parallel) ----------------
__global__ void k_prep(const float* __restrict__ g1, const float* __restrict__ be1,
                       const float* __restrict__ m1, const float* __restrict__ v1,
                       const float* __restrict__ s_in_p, const float* __restrict__ w1c,
                       const float* __restrict__ g2, const float* __restrict__ be2,
                       const float* __restrict__ m2, const float* __restrict__ v2,
                       const float* __restrict__ w2c)
{
    int t = threadIdx.x;
    int w = t >> 5, l = t & 31;
    if (blockIdx.x == 0) {
        if (t == 0) { g_max1 = 0u; g_max2 = 0u; g_maxb = 0u; g_maxy = 0u; }
        float w1 = g1[t] / sqrtf(v1[t] + 1e-5f);
        float b1 = be1[t] - m1[t] * w1;
        float bm = blockReduceMax(fabsf(w1));
        __shared__ float s_sbn;
        if (t == 0) s_sbn = bm / 127.0f + 1e-8f;
        __syncthreads();
        float sbn = s_sbn;
        float c = qclipf(rintf(w1 / sbn), -128.0f, 127.0f);
        g_w1q[t] = c * sbn;
        float sc = s_in_p[0] * sbn;
        g_b1q[t] = rintf(b1 / sc) * sc;
    } else if (blockIdx.x == 1) {
        for (int o = w; o < CO1; o += 8) {
            float tt = g2[o] / sqrtf(v2[o] + 1e-5f);
            const float* wr = w1c + o * CIN;
            float mx = 0.0f;
            #pragma unroll
            for (int i = 0; i < 8; i++) mx = fmaxf(mx, fabsf(wr[l + 32 * i] * tt));
            mx = warpMax(mx);
            float s = mx / 127.0f + 1e-8f;
            if (l == 0) { g_sw1[o] = s; g_bf[o] = be2[o] - m2[o] * tt; }
            #pragma unroll
            for (int i = 0; i < 8; i++) {
                int c = l + 32 * i;
                float code = qclipf(rintf(wr[c] * tt / s), -128.0f, 127.0f);
                g_w1cb[o * 256 + c] = __float2bfloat16(code);
            }
        }
    } else {
        for (int o = w; o < CO2; o += 8) {
            const float* wr = w2c + o * 1152;
            float mx = 0.0f;
            #pragma unroll
            for (int i = 0; i < 36; i++) mx = fmaxf(mx, fabsf(wr[l + 32 * i]));
            mx = warpMax(mx);
            float s = mx / 127.0f + 1e-8f;
            if (l == 0) g_sw2[o] = s;
            #pragma unroll
            for (int i = 0; i < 36; i++) {
                int j = l + 32 * i;
                int tap = j >> 7, ci = j & 127;
                float code = qclipf(rintf(wr[ci * 9 + tap] / s), -128.0f, 127.0f);
                g_w2cb[o * 1160 + j] = __float2bfloat16(code);
            }
        }
    }
}

// ------- K1: max relu(bn1(batch)) and max|batch|, plane-per-block, MLP=4 -----
__global__ __launch_bounds__(256) void k_max1(const float4* __restrict__ batch4)
{
    int ci = blockIdx.x, b = blockIdx.y;
    const float4* p = batch4 + (b * CIN + ci) * HW4;
    float w = g_w1q[ci], bb = g_b1q[ci];
    int t = threadIdx.x;
    float4 v0 = p[t], v1 = p[t + 256], v2 = p[t + 512];
    bool has3 = t < (HW4 - 768);
    float4 v3 = has3 ? p[t + 768] : make_float4(0.0f, 0.0f, 0.0f, 0.0f);
    float m1 = 0.0f, mb = 0.0f;
    #define M1(v) do { \
        m1 = fmaxf(m1, fmaxf(fmaf(v.x, w, bb), 0.0f)); \
        m1 = fmaxf(m1, fmaxf(fmaf(v.y, w, bb), 0.0f)); \
        m1 = fmaxf(m1, fmaxf(fmaf(v.z, w, bb), 0.0f)); \
        m1 = fmaxf(m1, fmaxf(fmaf(v.w, w, bb), 0.0f)); \
        mb = fmaxf(mb, fmaxf(fmaxf(fabsf(v.x), fabsf(v.y)), \
                             fmaxf(fabsf(v.z), fabsf(v.w)))); } while (0)
    M1(v0); M1(v1); M1(v2);
    if (has3) M1(v3);
    #undef M1
    float r1 = blockReduceMax(m1);
    if (t == 0) atomicMax(&g_max1, __float_as_uint(r1));
    float rb = blockReduceMax(mb);
    if (t == 0) atomicMax(&g_maxb, __float_as_uint(rb));
}

// ---- K2: fused bn1+quant + 1x1 conv via bf16 mma (128px x 128oc, K=256) ----
// W double-buffered (4 chunks of 64 ci); epilogue transposed via smem.
__global__ __launch_bounds__(256, 2) void k_conv1(const float* __restrict__ batch)
{
    extern __shared__ __nv_bfloat16 smemb[];
    __nv_bfloat16* Xs = smemb;                          // [128 px][264]
    __nv_bfloat16* Wb = smemb + 128 * 264;              // [2][128 oc][72]
    float* sc1  = (float*)(smemb + 128 * 264 + 2 * 128 * 72);
    float* sb1  = sc1 + 128;
    float* sw1s = sb1 + 128;                            // 256
    float* sb1s = sw1s + 256;                           // 256
    int t = threadIdx.x;
    int p0 = blockIdx.x * 128;

    float sa1 = __uint_as_float(g_max1) / 127.0f + 1e-8f;
    float inv = 1.0f / sa1;
    if (t < 128) {
        float sc = sa1 * g_sw1[t];
        sc1[t] = sc;
        sb1[t] = rintf(g_bf[t] / sc) * sc;
    }
    sw1s[t] = g_w1q[t];
    sb1s[t] = g_b1q[t];
    __syncthreads();

    // X staging: 8192 = 64 kwords x 128 px
    #pragma unroll
    for (int i = 0; i < 32; i++) {
        int lin = t + 256 * i;
        int k = lin >> 7, px = lin & 127;
        int pglob = p0 + px;
        int b = pglob / HW;
        int s = pglob - b * HW;
        const float* bp = batch + ((size_t)(b * CIN + 4 * k)) * HW + s;
        float f0 = bp[0], f1 = bp[HW], f2 = bp[2 * HW], f3 = bp[3 * HW];
        float4 wv = *(const float4*)&sw1s[4 * k];
        float4 bv = *(const float4*)&sb1s[4 * k];
        float q0 = qclipf(rintf(fmaxf(fmaf(f0, wv.x, bv.x), 0.0f) * inv), 0.0f, 127.0f);
        float q1 = qclipf(rintf(fmaxf(fmaf(f1, wv.y, bv.y), 0.0f) * inv), 0.0f, 127.0f);
        float q2 = qclipf(rintf(fmaxf(fmaf(f2, wv.z, bv.z), 0.0f) * inv), 0.0f, 127.0f);
        float q3 = qclipf(rintf(fmaxf(fmaf(f3, wv.w, bv.w), 0.0f) * inv), 0.0f, 127.0f);
        __nv_bfloat162 h01 = __floats2bfloat162_rn(q0, q1);
        __nv_bfloat162 h23 = __floats2bfloat162_rn(q2, q3);
        uint2 pk;
        pk.x = *(uint32_t*)&h01;
        pk.y = *(uint32_t*)&h23;
        *(uint2*)(Xs + px * 264 + 4 * k) = pk;
    }
    // W chunk 0: 1024 uint4
    #pragma unroll
    for (int i = 0; i < 4; i++) {
        int lin = t + 256 * i;
        int oc = lin >> 3, j = lin & 7;
        *(uint4*)(Wb + oc * 72 + j * 8) = ((const uint4*)(g_w1cb + oc * 256))[j];
    }
    __syncthreads();

    // 8 warps = 2 px-groups(64) x 4 oc-groups(32)
    int wid = t >> 5, l = t & 31;
    int pxg = wid & 1, ocg = wid >> 1;
    uint32_t xs0 = smem_u32(Xs), wb0 = smem_u32(Wb);

    uint32_t aaddr[4], boff4[2];
    #pragma unroll
    for (int mf = 0; mf < 4; mf++)
        aaddr[mf] = xs0 + ((pxg * 64 + mf * 16 + (l & 15)) * 264 + (l >> 4) * 8) * 2;
    #pragma unroll
    for (int np = 0; np < 2; np++)
        boff4[np] = ((ocg * 32 + np * 16 + ((l >> 4) & 1) * 8 + (l & 7)) * 72
                     + ((l >> 3) & 1) * 8) * 2;

    float acc[4][4][4];
    #pragma unroll
    for (int mf = 0; mf < 4; mf++)
        #pragma unroll
        for (int nf = 0; nf < 4; nf++)
            #pragma unroll
            for (int r = 0; r < 4; r++) acc[mf][nf][r] = 0.0f;

    #pragma unroll 1
    for (int c = 0; c < 4; c++) {
        if (c < 3) {
            int p1 = (c + 1) & 1;
            #pragma unroll
            for (int i = 0; i < 4; i++) {
                int lin = t + 256 * i;
                int oc = lin >> 3, j = lin & 7;
                *(uint4*)(Wb + p1 * 128 * 72 + oc * 72 + j * 8) =
                    ((const uint4*)(g_w1cb + oc * 256 + (c + 1) * 64))[j];
            }
        }
        uint32_t wbp = wb0 + (uint32_t)((c & 1) * 128 * 72 * 2);
        #pragma unroll
        for (int ksl = 0; ksl < 4; ksl++) {
            int ks = c * 4 + ksl;
            uint32_t a[4][4], bfr[4][2];
            #pragma unroll
            for (int mf = 0; mf < 4; mf++)
                ldsm_x4(a[mf][0], a[mf][1], a[mf][2], a[mf][3], aaddr[mf] + ks * 32);
            #pragma unroll
            for (int np = 0; np < 2; np++)
                ldsm_x4(bfr[2*np][0], bfr[2*np][1], bfr[2*np+1][0], bfr[2*np+1][1],
                        wbp + boff4[np] + ksl * 32);
            #pragma unroll
            for (int mf = 0; mf < 4; mf++)
                #pragma unroll
                for (int nf = 0; nf < 4; nf++)
                    mma_bf16(acc[mf][nf], a[mf], bfr[nf]);
        }
        __syncthreads();
    }

    // epilogue: scale+bias+relu into smem [128 px][132], then coalesced write
    float* outs = (float*)Xs;          // 128*132*4 = 67584 = Xs size
    float m = 0.0f;
    #pragma unroll
    for (int mf = 0; mf < 4; mf++) {
        int pxl = pxg * 64 + mf * 16 + (l >> 2);
        #pragma unroll
        for (int nf = 0; nf < 4; nf++) {
            int oc = ocg * 32 + nf * 8 + (l & 3) * 2;
            float s0 = sc1[oc], s1 = sc1[oc + 1];
            float bb0 = sb1[oc], bb1 = sb1[oc + 1];
            float v0 = fmaxf(fmaf(acc[mf][nf][0], s0, bb0), 0.0f);
            float v1 = fmaxf(fmaf(acc[mf][nf][1], s1, bb1), 0.0f);
            float v2 = fmaxf(fmaf(acc[mf][nf][2], s0, bb0), 0.0f);
            float v3 = fmaxf(fmaf(acc[mf][nf][3], s1, bb1), 0.0f);
            m = fmaxf(m, fmaxf(fmaxf(v0, v1), fmaxf(v2, v3)));
            *(float2*)&outs[pxl * 132 + oc]       = make_float2(v0, v1);
            *(float2*)&outs[(pxl + 8) * 132 + oc] = make_float2(v2, v3);
        }
    }
    __syncthreads();
    #pragma unroll
    for (int i = 0; i < 16; i++) {
        int lin = t + 256 * i;               // 4096 float4
        int pxl = lin >> 5, j = lin & 31;
        float4 v = *(float4*)&outs[pxl * 132 + j * 4];
        *(float4*)&g_x2[(size_t)(p0 + pxl) * 128 + j * 4] = v;
    }
    float bm = blockReduceMax(m);
    if (t == 0) atomicMax(&g_max2, __float_as_uint(bm));
}

// ---- K3: conv2 3x3 via bf16 mma, fused quant, per-tap W double buffer ----
__global__ __launch_bounds__(512, 2) void k_conv2(float* __restrict__ out)
{
    extern __shared__ __nv_bfloat16 smem2[];
    __nv_bfloat16* Xs = smem2;                          // [6][58][136] = 47328
    __nv_bfloat16* Wb = smem2 + 6 * 58 * 136;           // [2][32 oc][136]
    float* scmb = (float*)(Wb + 2 * 32 * 136);          // 32
    int t = threadIdx.x;
    int h0 = blockIdx.x * 4, b = blockIdx.y;

    float sa2 = __uint_as_float(g_max2) / 127.0f + 1e-8f;
    float inv2 = 1.0f / sa2;
    if (t < 32) scmb[t] = sa2 * g_sw2[t];

    // X staging with fused quantization
    for (int lin = t; lin < 6 * 58 * 32; lin += 512) {
        int cell = lin >> 5, j = lin & 31;
        int row = cell / 58, col = cell - row * 58;
        int hh = h0 + row - 1;
        float4 v = make_float4(0.0f, 0.0f, 0.0f, 0.0f);
        if (col >= 1 && col <= 56 && hh >= 0 && hh < 56)
            v = ((const float4*)(g_x2 + (size_t)(b * HW + hh * 56 + col - 1) * 128))[j];
        float q0 = qclipf(rintf(v.x * inv2), 0.0f, 127.0f);
        float q1 = qclipf(rintf(v.y * inv2), 0.0f, 127.0f);
        float q2 = qclipf(rintf(v.z * inv2), 0.0f, 127.0f);
        float q3 = qclipf(rintf(v.w * inv2), 0.0f, 127.0f);
        __nv_bfloat162 h01 = __floats2bfloat162_rn(q0, q1);
        __nv_bfloat162 h23 = __floats2bfloat162_rn(q2, q3);
        uint2 pk;
        pk.x = *(uint32_t*)&h01;
        pk.y = *(uint32_t*)&h23;
        *(uint2*)(Xs + cell * 136 + j * 4) = pk;
    }
    // W tap 0
    {
        int oc = t >> 4, j = t & 15;
        *(uint4*)(Wb + oc * 136 + j * 8) = ((const uint4*)(g_w2cb + oc * 1160))[j];
    }
    __syncthreads();

    int wid = t >> 5, l = t & 31;
    float m = 0.0f;
    float vv[4][4];
    uint32_t xs0 = smem_u32(Xs), wb0 = smem_u32(Wb);
    int px = wid * 16 + (l & 15);
    int hl = px / 56, ww = px - hl * 56;
    uint32_t abase = xs0 + ((hl * 58 + ww) * 136 + (l >> 4) * 8) * 2;
    uint32_t boff4[2];
    #pragma unroll
    for (int np = 0; np < 2; np++)
        boff4[np] = ((np * 16 + ((l >> 4) & 1) * 8 + (l & 7)) * 136
                     + ((l >> 3) & 1) * 8) * 2;

    float acc[4][4];
    #pragma unroll
    for (int nf = 0; nf < 4; nf++)
        #pragma unroll
        for (int r = 0; r < 4; r++) acc[nf][r] = 0.0f;

    #pragma unroll 1
    for (int tap = 0; tap < 9; tap++) {
        if (tap < 8) {
            int p1 = (tap + 1) & 1;
            int oc = t >> 4, j = t & 15;
            *(uint4*)(Wb + p1 * 32 * 136 + oc * 136 + j * 8) =
                ((const uint4*)(g_w2cb + oc * 1160 + (tap + 1) * 128))[j];
        }
        if (wid < 14) {
            uint32_t toff = (uint32_t)(((tap / 3) * 58 + (tap % 3)) * 136 * 2);
            uint32_t wbp = wb0 + (uint32_t)((tap & 1) * 32 * 136 * 2);
            #pragma unroll
            for (int ks = 0; ks < 8; ks++) {
                uint32_t a[4], bfr[4][2];
                ldsm_x4(a[0], a[1], a[2], a[3], abase + toff + ks * 32);
                #pragma unroll
                for (int np = 0; np < 2; np++)
                    ldsm_x4(bfr[2*np][0], bfr[2*np][1], bfr[2*np+1][0], bfr[2*np+1][1],
                            wbp + boff4[np] + ks * 32);
                #pragma unroll
                for (int nf = 0; nf < 4; nf++)
                    mma_bf16(acc[nf], a, bfr[nf]);
            }
        }
        __syncthreads();
    }
    if (wid < 14) {
        #pragma unroll
        for (int nf = 0; nf < 4; nf++) {
            int oc = nf * 8 + (l & 3) * 2;
            float s0 = scmb[oc], s1 = scmb[oc + 1];
            vv[nf][0] = acc[nf][0] * s0;
            vv[nf][1] = acc[nf][1] * s1;
            vv[nf][2] = acc[nf][2] * s0;
            vv[nf][3] = acc[nf][3] * s1;
            m = fmaxf(m, fmaxf(fmaxf(fabsf(vv[nf][0]), fabsf(vv[nf][1])),
                               fmaxf(fabsf(vv[nf][2]), fabsf(vv[nf][3]))));
        }
    }
    __syncthreads();                  // done reading Xs
    float* outs = (float*)Xs;         // [32 oc][228] floats
    if (wid < 14) {
        int pxo = wid * 16 + (l >> 2);
        #pragma unroll
        for (int nf = 0; nf < 4; nf++) {
            int oc = nf * 8 + (l & 3) * 2;
            outs[oc * 228 + pxo]           = vv[nf][0];
            outs[(oc + 1) * 228 + pxo]     = vv[nf][1];
            outs[oc * 228 + pxo + 8]       = vv[nf][2];
            outs[(oc + 1) * 228 + pxo + 8] = vv[nf][3];
        }
    }
    __syncthreads();
    size_t obase = ((size_t)b * 288 + 256) * HW + h0 * 56;
    for (int lin = t; lin < 32 * 56; lin += 512) {
        int oc = lin / 56, j = lin - oc * 56;
        float4 v = *(float4*)(outs + oc * 228 + j * 4);
        *(float4*)(out + obase + (size_t)oc * HW + j * 4) = v;
    }
    float bm = blockReduceMax(m);
    if (t == 0) atomicMax(&g_maxy, __float_as_uint(bm));
}

// ------ K4: output requant, plane-per-block, MLP=4, streaming hints --------
__global__ __launch_bounds__(256) void k_out(const float4* __restrict__ batch4,
                                             float4* __restrict__ out4,
                                             float* __restrict__ out, int out_size)
{
    int c = blockIdx.x, b = blockIdx.y;
    float s = fmaxf(__uint_as_float(g_maxb), __uint_as_float(g_maxy)) / 127.0f + 1e-8f;
    float inv = 1.0f / s;
    int t = threadIdx.x;
    float4* dst = out4 + (b * 288 + c) * HW4;
    const float4* src = (c < CIN) ? (batch4 + (b * CIN + c) * HW4) : dst;
    float4 v0 = __ldcs(&src[t]), v1 = __ldcs(&src[t + 256]), v2 = __ldcs(&src[t + 512]);
    bool has3 = t < (HW4 - 768);
    float4 v3 = has3 ? __ldcs(&src[t + 768]) : make_float4(0.0f, 0.0f, 0.0f, 0.0f);
    #define RQ(v) do { \
        v.x = qclipf(rintf(v.x * inv), -128.0f, 127.0f) * s; \
        v.y = qclipf(rintf(v.y * inv), -128.0f, 127.0f) * s; \
        v.z = qclipf(rintf(v.z * inv), -128.0f, 127.0f) * s; \
        v.w = qclipf(rintf(v.w * inv), -128.0f, 127.0f) * s; } while (0)
    RQ(v0); RQ(v1); RQ(v2);
    __stcs(&dst[t], v0); __stcs(&dst[t + 256], v1); __stcs(&dst[t + 512], v2);
    if (has3) { RQ(v3); __stcs(&dst[t + 768], v3); }
    #undef RQ
    if (c == 0 && b == 0 && t == 0)
        for (int k = N_OUT; k < out_size; k++) out[k] = s;
}

extern "C" void kernel_launch(void* const* d_in, const int* in_sizes, int n_in,
                              void* d_out, int out_size)
{
    const float* batch = (const float*)d_in[0];
    const float* s_in  = (const float*)d_in[1];
    const float* g1    = (const float*)d_in[2];
    const float* be1   = (const float*)d_in[3];
    const float* m1    = (const float*)d_in[4];
    const float* v1    = (const float*)d_in[5];
    const float* w1c   = (const float*)d_in[6];
    const float* g2    = (const float*)d_in[7];
    const float* be2   = (const float*)d_in[8];
    const float* m2    = (const float*)d_in[9];
    const float* v2    = (const float*)d_in[10];
    const float* w2c   = (const float*)d_in[11];
    float* out = (float*)d_out;

    const int CONV1_SMEM = 128 * 264 * 2 + 2 * 128 * 72 * 2
                         + (128 + 128 + 256 + 256) * 4;                 // 107520
    const int CONV2_SMEM = (6 * 58 * 136 + 2 * 32 * 136) * 2 + 32 * 4;  // 112192
    static bool attr_done = false;
    if (!attr_done) {
        cudaFuncSetAttribute(k_conv1, cudaFuncAttributeMaxDynamicSharedMemorySize, CONV1_SMEM);
        cudaFuncSetAttribute(k_conv2, cudaFuncAttributeMaxDynamicSharedMemorySize, CONV2_SMEM);
        attr_done = true;
    }

    k_prep<<<3, 256>>>(g1, be1, m1, v1, s_in, w1c, g2, be2, m2, v2, w2c);  // 0
    k_max1<<<dim3(CIN, B_N), 256>>>((const float4*)batch);                 // 1
    k_conv1<<<PX / 128, 256, CONV1_SMEM>>>(batch);                         // 2
    k_conv2<<<dim3(14, 32), 512, CONV2_SMEM>>>(out);                       // 3 (profiled)
    k_out<<<dim3(288, B_N), 256>>>((const float4*)batch, (float4*)out, out, out_size);
}

// round 11
// speedup vs baseline: 2.1760x; 1.0375x over previous
#include <cuda_runtime.h>
#include <cuda_bf16.h>
#include <cstdint>

#define B_N   32
#define CIN   256
#define HW    3136
#define HW4   784
#define PX    100352          // B_N*HW
#define CO1   128
#define CO2   32
#define N_OUT (32*288*3136)

// ---------------- scratch (device globals; no allocations) ----------------
__device__ float    g_w1q[CIN], g_b1q[CIN];
__device__ float    g_bf[CO1], g_sw1[CO1];
__device__ __nv_bfloat16 g_w1cb[CO1*256];   // conv1 weight codes bf16 [oc][k]
__device__ float    g_sw2[CO2];
__device__ __nv_bfloat16 g_w2cb[CO2*1160];  // conv2 weight codes bf16 [oc][tap*128+ci]
__device__ unsigned g_max1, g_max2, g_maxb, g_maxy;
__device__ float    g_x2[PX*CO1];           // conv1 out fp32 NHWC (51.4MB)

// ---------------- helpers ----------------
__device__ __forceinline__ float warpMax(float v) {
    #pragma unroll
    for (int o = 16; o; o >>= 1) v = fmaxf(v, __shfl_xor_sync(0xffffffffu, v, o));
    return v;
}
__device__ __forceinline__ float blockReduceMax(float v) {
    __shared__ float sm[16];
    float w = warpMax(v);
    if ((threadIdx.x & 31) == 0) sm[threadIdx.x >> 5] = w;
    __syncthreads();
    float r = (threadIdx.x < (blockDim.x >> 5)) ? sm[threadIdx.x] : 0.0f;
    r = warpMax(r);
    __syncthreads();
    return r;  // valid in warp 0
}
__device__ __forceinline__ float qclipf(float q, float lo, float hi) {
    return fminf(fmaxf(q, lo), hi);
}
__device__ __forceinline__ uint32_t smem_u32(const void* p) {
    return (uint32_t)__cvta_generic_to_shared(p);
}
__device__ __forceinline__ void ldsm_x4(uint32_t& r0, uint32_t& r1,
                                        uint32_t& r2, uint32_t& r3, uint32_t a) {
    asm volatile("ldmatrix.sync.aligned.m8n8.x4.shared.b16 {%0,%1,%2,%3}, [%4];"
                 : "=r"(r0), "=r"(r1), "=r"(r2), "=r"(r3) : "r"(a));
}
__device__ __forceinline__ void mma_bf16(float* d, const uint32_t* a, const uint32_t* b) {
    asm volatile(
        "mma.sync.aligned.m16n8k16.row.col.f32.bf16.bf16.f32 "
        "{%0,%1,%2,%3},{%4,%5,%6,%7},{%8,%9},{%0,%1,%2,%3};"
        : "+f"(d[0]), "+f"(d[1]), "+f"(d[2]), "+f"(d[3])
        : "r"(a[0]), "r"(a[1]), "r"(a[2]), "r"(a[3]), "r"(b[0]), "r"(b[1]));
}
__device__ __forceinline__ void cp16(uint32_t dst, const void* src) {
    asm volatile("cp.async.cg.shared.global [%0], [%1], 16;" :: "r"(dst), "l"(src));
}
__device__ __forceinline__ void cp_commit() {
    asm volatile("cp.async.commit_group;");
}
__device__ __forceinline__ void cp_wait0() {
    asm volatile("cp.async.wait_group 0;" ::: "memory");
}
__device__ __forceinline__ void bar_sync(int id) {
    asm volatile("bar.sync %0, 512;" :: "r"(id) : "memory");
}
__device__ __forceinline__ void bar_arrive(int id) {
    asm volatile("bar.arrive %0, 512;" :: "r"(id) : "memory");
}

// ---------------- K0: all weight prep (3 blocks, warp-parallel) ----------------
__global__ void k_prep(const float* __restrict__ g1, const float* __restrict__ be1,
                       const float* __restrict__ m1, const float* __restrict__ v1,
                       const float* __restrict__ s_in_p, const float* __restrict__ w1c,
                       const float* __restrict__ g2, const float* __restrict__ be2,
                       const float* __restrict__ m2, const float* __restrict__ v2,
                       const float* __restrict__ w2c)
{
    int t = threadIdx.x;
    int w = t >> 5, l = t & 31;
    if (blockIdx.x == 0) {
        if (t == 0) { g_max1 = 0u; g_max2 = 0u; g_maxb = 0u; g_maxy = 0u; }
        float w1 = g1[t] / sqrtf(v1[t] + 1e-5f);
        float b1 = be1[t] - m1[t] * w1;
        float bm = blockReduceMax(fabsf(w1));
        __shared__ float s_sbn;
        if (t == 0) s_sbn = bm / 127.0f + 1e-8f;
        __syncthreads();
        float sbn = s_sbn;
        float c = qclipf(rintf(w1 / sbn), -128.0f, 127.0f);
        g_w1q[t] = c * sbn;
        float sc = s_in_p[0] * sbn;
        g_b1q[t] = rintf(b1 / sc) * sc;
    } else if (blockIdx.x == 1) {
        for (int o = w; o < CO1; o += 8) {
            float tt = g2[o] / sqrtf(v2[o] + 1e-5f);
            const float* wr = w1c + o * CIN;
            float mx = 0.0f;
            #pragma unroll
            for (int i = 0; i < 8; i++) mx = fmaxf(mx, fabsf(wr[l + 32 * i] * tt));
            mx = warpMax(mx);
            float s = mx / 127.0f + 1e-8f;
            if (l == 0) { g_sw1[o] = s; g_bf[o] = be2[o] - m2[o] * tt; }
            #pragma unroll
            for (int i = 0; i < 8; i++) {
                int c = l + 32 * i;
                float code = qclipf(rintf(wr[c] * tt / s), -128.0f, 127.0f);
                g_w1cb[o * 256 + c] = __float2bfloat16(code);
            }
        }
    } else {
        for (int o = w; o < CO2; o += 8) {
            const float* wr = w2c + o * 1152;
            float mx = 0.0f;
            #pragma unroll
            for (int i = 0; i < 36; i++) mx = fmaxf(mx, fabsf(wr[l + 32 * i]));
            mx = warpMax(mx);
            float s = mx / 127.0f + 1e-8f;
            if (l == 0) g_sw2[o] = s;
            #pragma unroll
            for (int i = 0; i < 36; i++) {
                int j = l + 32 * i;
                int tap = j >> 7, ci = j & 127;
                float code = qclipf(rintf(wr[ci * 9 + tap] / s), -128.0f, 127.0f);
                g_w2cb[o * 1160 + j] = __float2bfloat16(code);
            }
        }
    }
}

// ------- K1: max relu(bn1(batch)) and max|batch|, plane-per-block, MLP=4 -----
__global__ __launch_bounds__(256) void k_max1(const float4* __restrict__ batch4)
{
    int ci = blockIdx.x, b = blockIdx.y;
    const float4* p = batch4 + (b * CIN + ci) * HW4;
    float w = g_w1q[ci], bb = g_b1q[ci];
    int t = threadIdx.x;
    float4 v0 = p[t], v1 = p[t + 256], v2 = p[t + 512];
    bool has3 = t < (HW4 - 768);
    float4 v3 = has3 ? p[t + 768] : make_float4(0.0f, 0.0f, 0.0f, 0.0f);
    float m1 = 0.0f, mb = 0.0f;
    #define M1(v) do { \
        m1 = fmaxf(m1, fmaxf(fmaf(v.x, w, bb), 0.0f)); \
        m1 = fmaxf(m1, fmaxf(fmaf(v.y, w, bb), 0.0f)); \
        m1 = fmaxf(m1, fmaxf(fmaf(v.z, w, bb), 0.0f)); \
        m1 = fmaxf(m1, fmaxf(fmaf(v.w, w, bb), 0.0f)); \
        mb = fmaxf(mb, fmaxf(fmaxf(fabsf(v.x), fabsf(v.y)), \
                             fmaxf(fabsf(v.z), fabsf(v.w)))); } while (0)
    M1(v0); M1(v1); M1(v2);
    if (has3) M1(v3);
    #undef M1
    float r1 = blockReduceMax(m1);
    if (t == 0) atomicMax(&g_max1, __float_as_uint(r1));
    float rb = blockReduceMax(mb);
    if (t == 0) atomicMax(&g_maxb, __float_as_uint(rb));
}

// ---- K2: fused bn1+quant + 1x1 conv via bf16 mma (128px x 128oc, K=256) ----
// W double-buffered via cp.async (4 chunks of 64 ci); smem epilogue.
__global__ __launch_bounds__(256, 2) void k_conv1(const float* __restrict__ batch)
{
    extern __shared__ __nv_bfloat16 smemb[];
    __nv_bfloat16* Xs = smemb;                          // [128 px][264]
    __nv_bfloat16* Wb = smemb + 128 * 264;              // [2][128 oc][72]
    float* sc1  = (float*)(smemb + 128 * 264 + 2 * 128 * 72);
    float* sb1  = sc1 + 128;
    float* sw1s = sb1 + 128;                            // 256
    float* sb1s = sw1s + 256;                           // 256
    int t = threadIdx.x;
    int p0 = blockIdx.x * 128;

    float sa1 = __uint_as_float(g_max1) / 127.0f + 1e-8f;
    float inv = 1.0f / sa1;
    if (t < 128) {
        float sc = sa1 * g_sw1[t];
        sc1[t] = sc;
        sb1[t] = rintf(g_bf[t] / sc) * sc;
    }
    sw1s[t] = g_w1q[t];
    sb1s[t] = g_b1q[t];

    // W chunk 0 via cp.async (overlaps with X staging below)
    #pragma unroll
    for (int i = 0; i < 4; i++) {
        int lin = t + 256 * i;
        int oc = lin >> 3, j = lin & 7;
        cp16(smem_u32(Wb + oc * 72 + j * 8),
             (const void*)(((const uint4*)(g_w1cb + oc * 256)) + j));
    }
    cp_commit();
    __syncthreads();   // scales visible

    // X staging: 8192 = 64 kwords x 128 px
    #pragma unroll
    for (int i = 0; i < 32; i++) {
        int lin = t + 256 * i;
        int k = lin >> 7, px = lin & 127;
        int pglob = p0 + px;
        int b = pglob / HW;
        int s = pglob - b * HW;
        const float* bp = batch + ((size_t)(b * CIN + 4 * k)) * HW + s;
        float f0 = bp[0], f1 = bp[HW], f2 = bp[2 * HW], f3 = bp[3 * HW];
        float4 wv = *(const float4*)&sw1s[4 * k];
        float4 bv = *(const float4*)&sb1s[4 * k];
        float q0 = qclipf(rintf(fmaxf(fmaf(f0, wv.x, bv.x), 0.0f) * inv), 0.0f, 127.0f);
        float q1 = qclipf(rintf(fmaxf(fmaf(f1, wv.y, bv.y), 0.0f) * inv), 0.0f, 127.0f);
        float q2 = qclipf(rintf(fmaxf(fmaf(f2, wv.z, bv.z), 0.0f) * inv), 0.0f, 127.0f);
        float q3 = qclipf(rintf(fmaxf(fmaf(f3, wv.w, bv.w), 0.0f) * inv), 0.0f, 127.0f);
        __nv_bfloat162 h01 = __floats2bfloat162_rn(q0, q1);
        __nv_bfloat162 h23 = __floats2bfloat162_rn(q2, q3);
        uint2 pk;
        pk.x = *(uint32_t*)&h01;
        pk.y = *(uint32_t*)&h23;
        *(uint2*)(Xs + px * 264 + 4 * k) = pk;
    }
    cp_wait0();
    __syncthreads();

    // 8 warps = 2 px-groups(64) x 4 oc-groups(32)
    int wid = t >> 5, l = t & 31;
    int pxg = wid & 1, ocg = wid >> 1;
    uint32_t xs0 = smem_u32(Xs), wb0 = smem_u32(Wb);

    uint32_t aaddr[4], boff4[2];
    #pragma unroll
    for (int mf = 0; mf < 4; mf++)
        aaddr[mf] = xs0 + ((pxg * 64 + mf * 16 + (l & 15)) * 264 + (l >> 4) * 8) * 2;
    #pragma unroll
    for (int np = 0; np < 2; np++)
        boff4[np] = ((ocg * 32 + np * 16 + ((l >> 4) & 1) * 8 + (l & 7)) * 72
                     + ((l >> 3) & 1) * 8) * 2;

    float acc[4][4][4];
    #pragma unroll
    for (int mf = 0; mf < 4; mf++)
        #pragma unroll
        for (int nf = 0; nf < 4; nf++)
            #pragma unroll
            for (int r = 0; r < 4; r++) acc[mf][nf][r] = 0.0f;

    #pragma unroll 1
    for (int c = 0; c < 4; c++) {
        if (c < 3) {
            int p1 = (c + 1) & 1;
            #pragma unroll
            for (int i = 0; i < 4; i++) {
                int lin = t + 256 * i;
                int oc = lin >> 3, j = lin & 7;
                cp16(smem_u32(Wb + p1 * 128 * 72 + oc * 72 + j * 8),
                     (const void*)(((const uint4*)(g_w1cb + oc * 256 + (c + 1) * 64)) + j));
            }
            cp_commit();
        }
        uint32_t wbp = wb0 + (uint32_t)((c & 1) * 128 * 72 * 2);
        #pragma unroll
        for (int ksl = 0; ksl < 4; ksl++) {
            int ks = c * 4 + ksl;
            uint32_t a[4][4], bfr[4][2];
            #pragma unroll
            for (int mf = 0; mf < 4; mf++)
                ldsm_x4(a[mf][0], a[mf][1], a[mf][2], a[mf][3], aaddr[mf] + ks * 32);
            #pragma unroll
            for (int np = 0; np < 2; np++)
                ldsm_x4(bfr[2*np][0], bfr[2*np][1], bfr[2*np+1][0], bfr[2*np+1][1],
                        wbp + boff4[np] + ksl * 32);
            #pragma unroll
            for (int mf = 0; mf < 4; mf++)
                #pragma unroll
                for (int nf = 0; nf < 4; nf++)
                    mma_bf16(acc[mf][nf], a[mf], bfr[nf]);
        }
        cp_wait0();
        __syncthreads();
    }

    // epilogue: scale+bias+relu into smem [128 px][132], then coalesced write
    float* outs = (float*)Xs;          // 128*132*4 = 67584 = Xs size
    float m = 0.0f;
    #pragma unroll
    for (int mf = 0; mf < 4; mf++) {
        int pxl = pxg * 64 + mf * 16 + (l >> 2);
        #pragma unroll
        for (int nf = 0; nf < 4; nf++) {
            int oc = ocg * 32 + nf * 8 + (l & 3) * 2;
            float s0 = sc1[oc], s1 = sc1[oc + 1];
            float bb0 = sb1[oc], bb1 = sb1[oc + 1];
            float v0 = fmaxf(fmaf(acc[mf][nf][0], s0, bb0), 0.0f);
            float v1 = fmaxf(fmaf(acc[mf][nf][1], s1, bb1), 0.0f);
            float v2 = fmaxf(fmaf(acc[mf][nf][2], s0, bb0), 0.0f);
            float v3 = fmaxf(fmaf(acc[mf][nf][3], s1, bb1), 0.0f);
            m = fmaxf(m, fmaxf(fmaxf(v0, v1), fmaxf(v2, v3)));
            *(float2*)&outs[pxl * 132 + oc]       = make_float2(v0, v1);
            *(float2*)&outs[(pxl + 8) * 132 + oc] = make_float2(v2, v3);
        }
    }
    __syncthreads();
    #pragma unroll
    for (int i = 0; i < 16; i++) {
        int lin = t + 256 * i;               // 4096 float4
        int pxl = lin >> 5, j = lin & 31;
        float4 v = *(float4*)&outs[pxl * 132 + j * 4];
        *(float4*)&g_x2[(size_t)(p0 + pxl) * 128 + j * 4] = v;
    }
    float bm = blockReduceMax(m);
    if (t == 0) atomicMax(&g_max2, __float_as_uint(bm));
}

// ---- K3: conv2 3x3 via bf16 mma, fused quant, producer/consumer W pipeline ----
// warps 14-15 stage W per tap with cp.async; warps 0-13 run mma gated by
// named barriers: ready[parity]=id 1+p, done[parity]=id 3+p (count 512).
__global__ __launch_bounds__(512, 2) void k_conv2(float* __restrict__ out)
{
    extern __shared__ __nv_bfloat16 smem2[];
    __nv_bfloat16* Xs = smem2;                          // [6][58][136] = 47328
    __nv_bfloat16* Wb = smem2 + 6 * 58 * 136;           // [2][32 oc][136]
    float* scmb = (float*)(Wb + 2 * 32 * 136);          // 32
    int t = threadIdx.x;
    int h0 = blockIdx.x * 4, b = blockIdx.y;

    float sa2 = __uint_as_float(g_max2) / 127.0f + 1e-8f;
    float inv2 = 1.0f / sa2;
    if (t < 32) scmb[t] = sa2 * g_sw2[t];

    // W tap 0 via cp.async (overlaps X staging)
    {
        int oc = t >> 4, j = t & 15;
        cp16(smem_u32(Wb + oc * 136 + j * 8),
             (const void*)(((const uint4*)(g_w2cb + oc * 1160)) + j));
        cp_commit();
    }
    // X staging with fused quantization
    for (int lin = t; lin < 6 * 58 * 32; lin += 512) {
        int cell = lin >> 5, j = lin & 31;
        int row = cell / 58, col = cell - row * 58;
        int hh = h0 + row - 1;
        float4 v = make_float4(0.0f, 0.0f, 0.0f, 0.0f);
        if (col >= 1 && col <= 56 && hh >= 0 && hh < 56)
            v = ((const float4*)(g_x2 + (size_t)(b * HW + hh * 56 + col - 1) * 128))[j];
        float q0 = qclipf(rintf(v.x * inv2), 0.0f, 127.0f);
        float q1 = qclipf(rintf(v.y * inv2), 0.0f, 127.0f);
        float q2 = qclipf(rintf(v.z * inv2), 0.0f, 127.0f);
        float q3 = qclipf(rintf(v.w * inv2), 0.0f, 127.0f);
        __nv_bfloat162 h01 = __floats2bfloat162_rn(q0, q1);
        __nv_bfloat162 h23 = __floats2bfloat162_rn(q2, q3);
        uint2 pk;
        pk.x = *(uint32_t*)&h01;
        pk.y = *(uint32_t*)&h23;
        *(uint2*)(Xs + cell * 136 + j * 4) = pk;
    }
    cp_wait0();
    __syncthreads();

    int wid = t >> 5, l = t & 31;
    float m = 0.0f;
    float vv[4][4];

    if (wid >= 14) {
        // -------- producer: stage W taps 1..8, double buffered --------
        int pt = t - 448;   // 0..63
        #pragma unroll 1
        for (int tap = 1; tap <= 8; tap++) {
            int bsel = tap & 1;
            if (tap >= 2) bar_sync(3 + bsel);       // consumers done with tap-2
            #pragma unroll
            for (int i = 0; i < 8; i++) {
                int idx = pt + 64 * i;
                int oc = idx >> 4, j = idx & 15;
                cp16(smem_u32(Wb + bsel * 32 * 136 + oc * 136 + j * 8),
                     (const void*)(((const uint4*)(g_w2cb + oc * 1160 + tap * 128)) + j));
            }
            cp_commit();
            cp_wait0();
            bar_arrive(1 + bsel);                   // buffer ready
        }
    } else {
        // -------- consumers: 14 mma warps --------
        uint32_t xs0 = smem_u32(Xs), wb0 = smem_u32(Wb);
        int px = wid * 16 + (l & 15);
        int hl = px / 56, ww = px - hl * 56;
        uint32_t abase = xs0 + ((hl * 58 + ww) * 136 + (l >> 4) * 8) * 2;
        uint32_t boff4[2];
        #pragma unroll
        for (int np = 0; np < 2; np++)
            boff4[np] = ((np * 16 + ((l >> 4) & 1) * 8 + (l & 7)) * 136
                         + ((l >> 3) & 1) * 8) * 2;

        float acc[4][4];
        #pragma unroll
        for (int nf = 0; nf < 4; nf++)
            #pragma unroll
            for (int r = 0; r < 4; r++) acc[nf][r] = 0.0f;

        #pragma unroll 1
        for (int tap = 0; tap <= 8; tap++) {
            int bsel = tap & 1;
            if (tap >= 1) bar_sync(1 + bsel);       // wait buffer ready
            uint32_t toff = (uint32_t)(((tap / 3) * 58 + (tap % 3)) * 136 * 2);
            uint32_t wbp = wb0 + (uint32_t)(bsel * 32 * 136 * 2);
            #pragma unroll
            for (int ks = 0; ks < 8; ks++) {
                uint32_t a[4], bfr[4][2];
                ldsm_x4(a[0], a[1], a[2], a[3], abase + toff + ks * 32);
                #pragma unroll
                for (int np = 0; np < 2; np++)
                    ldsm_x4(bfr[2*np][0], bfr[2*np][1], bfr[2*np+1][0], bfr[2*np+1][1],
                            wbp + boff4[np] + ks * 32);
                #pragma unroll
                for (int nf = 0; nf < 4; nf++)
                    mma_bf16(acc[nf], a, bfr[nf]);
            }
            bar_arrive(3 + bsel);                   // done with this buffer
        }
        #pragma unroll
        for (int nf = 0; nf < 4; nf++) {
            int oc = nf * 8 + (l & 3) * 2;
            float s0 = scmb[oc], s1 = scmb[oc + 1];
            vv[nf][0] = acc[nf][0] * s0;
            vv[nf][1] = acc[nf][1] * s1;
            vv[nf][2] = acc[nf][2] * s0;
            vv[nf][3] = acc[nf][3] * s1;
            m = fmaxf(m, fmaxf(fmaxf(fabsf(vv[nf][0]), fabsf(vv[nf][1])),
                               fmaxf(fabsf(vv[nf][2]), fabsf(vv[nf][3]))));
        }
    }
    __syncthreads();                  // all done reading Xs
    float* outs = (float*)Xs;         // [32 oc][228] floats
    if (wid < 14) {
        int pxo = wid * 16 + (l >> 2);
        #pragma unroll
        for (int nf = 0; nf < 4; nf++) {
            int oc = nf * 8 + (l & 3) * 2;
            outs[oc * 228 + pxo]           = vv[nf][0];
            outs[(oc + 1) * 228 + pxo]     = vv[nf][1];
            outs[oc * 228 + pxo + 8]       = vv[nf][2];
            outs[(oc + 1) * 228 + pxo + 8] = vv[nf][3];
        }
    }
    __syncthreads();
    size_t obase = ((size_t)b * 288 + 256) * HW + h0 * 56;
    for (int lin = t; lin < 32 * 56; lin += 512) {
        int oc = lin / 56, j = lin - oc * 56;
        float4 v = *(float4*)(outs + oc * 228 + j * 4);
        *(float4*)(out + obase + (size_t)oc * HW + j * 4) = v;
    }
    float bm = blockReduceMax(m);
    if (t == 0) atomicMax(&g_maxy, __float_as_uint(bm));
}

// ------ K4: output requant, plane-per-block, MLP=4, streaming hints --------
__global__ __launch_bounds__(256) void k_out(const float4* __restrict__ batch4,
                                             float4* __restrict__ out4,
                                             float* __restrict__ out, int out_size)
{
    int c = blockIdx.x, b = blockIdx.y;
    float s = fmaxf(__uint_as_float(g_maxb), __uint_as_float(g_maxy)) / 127.0f + 1e-8f;
    float inv = 1.0f / s;
    int t = threadIdx.x;
    float4* dst = out4 + (b * 288 + c) * HW4;
    const float4* src = (c < CIN) ? (batch4 + (b * CIN + c) * HW4) : dst;
    float4 v0 = __ldcs(&src[t]), v1 = __ldcs(&src[t + 256]), v2 = __ldcs(&src[t + 512]);
    bool has3 = t < (HW4 - 768);
    float4 v3 = has3 ? __ldcs(&src[t + 768]) : make_float4(0.0f, 0.0f, 0.0f, 0.0f);
    #define RQ(v) do { \
        v.x = qclipf(rintf(v.x * inv), -128.0f, 127.0f) * s; \
        v.y = qclipf(rintf(v.y * inv), -128.0f, 127.0f) * s; \
        v.z = qclipf(rintf(v.z * inv), -128.0f, 127.0f) * s; \
        v.w = qclipf(rintf(v.w * inv), -128.0f, 127.0f) * s; } while (0)
    RQ(v0); RQ(v1); RQ(v2);
    __stcs(&dst[t], v0); __stcs(&dst[t + 256], v1); __stcs(&dst[t + 512], v2);
    if (has3) { RQ(v3); __stcs(&dst[t + 768], v3); }
    #undef RQ
    if (c == 0 && b == 0 && t == 0)
        for (int k = N_OUT; k < out_size; k++) out[k] = s;
}

extern "C" void kernel_launch(void* const* d_in, const int* in_sizes, int n_in,
                              void* d_out, int out_size)
{
    const float* batch = (const float*)d_in[0];
    const float* s_in  = (const float*)d_in[1];
    const float* g1    = (const float*)d_in[2];
    const float* be1   = (const float*)d_in[3];
    const float* m1    = (const float*)d_in[4];
    const float* v1    = (const float*)d_in[5];
    const float* w1c   = (const float*)d_in[6];
    const float* g2    = (const float*)d_in[7];
    const float* be2   = (const float*)d_in[8];
    const float* m2    = (const float*)d_in[9];
    const float* v2    = (const float*)d_in[10];
    const float* w2c   = (const float*)d_in[11];
    float* out = (float*)d_out;

    const int CONV1_SMEM = 128 * 264 * 2 + 2 * 128 * 72 * 2
                         + (128 + 128 + 256 + 256) * 4;                 // 107520
    const int CONV2_SMEM = (6 * 58 * 136 + 2 * 32 * 136) * 2 + 32 * 4;  // 112192
    static bool attr_done = false;
    if (!attr_done) {
        cudaFuncSetAttribute(k_conv1, cudaFuncAttributeMaxDynamicSharedMemorySize, CONV1_SMEM);
        cudaFuncSetAttribute(k_conv2, cudaFuncAttributeMaxDynamicSharedMemorySize, CONV2_SMEM);
        attr_done = true;
    }

    k_prep<<<3, 256>>>(g1, be1, m1, v1, s_in, w1c, g2, be2, m2, v2, w2c);  // 0
    k_max1<<<dim3(CIN, B_N), 256>>>((const float4*)batch);                 // 1
    k_conv1<<<PX / 128, 256, CONV1_SMEM>>>(batch);                         // 2
    k_conv2<<<dim3(14, 32), 512, CONV2_SMEM>>>(out);                       // 3 (profiled)
    k_out<<<dim3(288, B_N), 256>>>((const float4*)batch, (float4*)out, out, out_size);
}